// round 13
// baseline (speedup 1.0000x reference)
#include <cuda_runtime.h>
#include <math.h>

// Problem constants (fixed by the dataset)
#define NN 50000
#define NE 800000
#define S  128

typedef unsigned long long ull;

// ---------------- scratch (device globals; referenced directly) ---------------
__device__ float g_xe [(size_t)NN * S];      // relu(x@Wn+bn)
__device__ float g_pxe[(size_t)NN * S];      // normalized-adjacency propagated xe
__device__ float g_ZH [(size_t)NN * 2 * S];  // pre-activation [z | h]
__device__ float g_deg [NN];
__device__ float g_dinv[NN];
__device__ float g_as[NN];                   // H . w0
__device__ float g_bs[NN];                   // H . w1
__device__ float g_Wcat[S * 2 * S];          // [128][256] = [Wzc@Wzl_top | Whc@Whl_top]
__device__ float g_bcat[2 * S];
__device__ int   g_src[NE];                  // decoded edge sources
__device__ int   g_dst[NE];                  // decoded edge destinations
__device__ int   g_eimode;                   // 1 = int64 input layout, 0 = int32

// ---------------- packed f32x2 helpers --------------------------------------
__device__ __forceinline__ ull pack2(float x, float y) {
    ull r; asm("mov.b64 %0, {%1,%2};" : "=l"(r) : "f"(x), "f"(y)); return r;
}
__device__ __forceinline__ void ffma2(ull &d, ull a, ull b) {
    asm("fma.rn.f32x2 %0, %1, %2, %0;" : "+l"(d) : "l"(a), "l"(b));
}
__device__ __forceinline__ float2 unpack2(ull v) {
    float2 f; asm("mov.b64 {%0,%1}, %2;" : "=f"(f.x), "=f"(f.y) : "l"(v)); return f;
}

// ---------------- edge-index dtype detection + decode -------------------------
// int64 entries (values < 2^31, little-endian): odd 32-bit words are all zero.
// int32 entries: odd words are random indices in [0,50000) -> ~never all zero.
// Samples are spread across the WHOLE array.
__global__ void ei_detect_k(const int* __restrict__ ei32, int E) {
    __shared__ int s_nonzero;
    if (threadIdx.x == 0) s_nonzero = 0;
    __syncthreads();
    int nsamp = 4096;
    if (nsamp > E) nsamp = E;
    int stride = (2 * E) / nsamp;   // in int64-entry units across both rows
    if (stride < 1) stride = 1;
    int bad = 0;
    for (int k = threadIdx.x; k < nsamp; k += blockDim.x) {
        size_t entry = (size_t)k * stride;          // entry index in [0, 2E)
        if (ei32[2 * entry + 1] != 0) bad = 1;      // high word of int64 entry
    }
    if (bad) atomicOr(&s_nonzero, 1);
    __syncthreads();
    if (threadIdx.x == 0) g_eimode = (s_nonzero == 0) ? 1 : 0;
}

__global__ void ei_decode_k(const int* __restrict__ ei32, int E, int n) {
    int e = blockIdx.x * blockDim.x + threadIdx.x;
    if (e >= E) return;
    int s, d;
    if (g_eimode) {   // int64 [2,E]: 32-bit word index 2*j for entry j
        s = ei32[2 * (size_t)e];
        d = ei32[2 * ((size_t)E + e)];
    } else {          // int32 [2,E]
        s = ei32[e];
        d = ei32[(size_t)E + e];
    }
    // defensive clamp: a wrong decode yields rel_err failure, never a trap
    s = min(max(s, 0), n - 1);
    d = min(max(d, 0), n - 1);
    g_src[e] = s;
    g_dst[e] = d;
}

// ---------------- weight folding --------------------------------------------
// g_Wcat[k][n] (n<128): sum_i Wzc[k][i] * Wzl[i][n]; (n>=128): Whc/Whl.
__global__ void prep_w_k(const float* __restrict__ Wzc, const float* __restrict__ Wzl,
                         const float* __restrict__ Whc, const float* __restrict__ Whl) {
    int k = blockIdx.x;          // 0..127
    int n = threadIdx.x;         // 0..255
    const float* Wc; const float* Wl; int nn;
    if (n < S) { Wc = Wzc + (size_t)k * S; Wl = Wzl; nn = n; }
    else       { Wc = Whc + (size_t)k * S; Wl = Whl; nn = n - S; }
    float s = 0.f;
    #pragma unroll 8
    for (int i = 0; i < S; i++) s += Wc[i] * Wl[(size_t)i * S + nn];
    g_Wcat[(size_t)k * 2 * S + n] = s;
}

__global__ void prep_b_k(const float* __restrict__ bzc, const float* __restrict__ Wzl,
                         const float* __restrict__ bzl,
                         const float* __restrict__ bhc, const float* __restrict__ Whl,
                         const float* __restrict__ bhl) {
    int n = threadIdx.x;
    const float* bc; const float* Wl; const float* bl; int nn;
    if (n < S) { bc = bzc; Wl = Wzl; bl = bzl; nn = n; }
    else       { bc = bhc; Wl = Whl; bl = bhl; nn = n - S; }
    float s = 0.f;
    #pragma unroll 8
    for (int i = 0; i < S; i++) s += bc[i] * Wl[(size_t)i * S + nn];
    g_bcat[n] = s + bl[nn];
}

// ---------------- degree / norm ----------------------------------------------
__global__ void deg_init_k(int n) {
    int i = blockIdx.x * blockDim.x + threadIdx.x;
    if (i < n) g_deg[i] = 1.0f;  // self loop
}
__global__ void deg_acc_k(int E) {
    int e = blockIdx.x * blockDim.x + threadIdx.x;
    if (e < E) atomicAdd(&g_deg[g_dst[e]], 1.0f);
}
__global__ void dinv_k(int n) {
    int i = blockIdx.x * blockDim.x + threadIdx.x;
    if (i < n) g_dinv[i] = rsqrtf(g_deg[i]);
}

// ---------------- fp32 GEMM body: C = act(A[M,K] @ B[K,128] + bias) ----------
// BM=128, BN=128, BK=8, 256 threads, 8x8 thread tiles, f32x2 packed FMA.
__device__ __forceinline__
void gemm_body(const float* __restrict__ A, int M, int K, int lda,
               const float* __restrict__ B, int ldb,
               const float* __restrict__ bias,
               float* __restrict__ C, int ldc, int act) {
    __shared__ float As[8][128];
    __shared__ float Bs[8][128];
    int tid = threadIdx.x;
    int tx = tid & 15, ty = tid >> 4;
    int m0 = blockIdx.x * 128;
    int lrow = tid >> 1;
    int lkq  = (tid & 1) * 4;
    int bk = tid >> 5;
    int bn = (tid & 31) * 4;

    ull acc[8][4];
    #pragma unroll
    for (int i = 0; i < 8; i++)
        #pragma unroll
        for (int j = 0; j < 4; j++) acc[i][j] = 0ull;

    for (int kk = 0; kk < K; kk += 8) {
        float4 av = make_float4(0.f, 0.f, 0.f, 0.f);
        int arow = m0 + lrow;
        if (arow < M) av = *(const float4*)(A + (size_t)arow * lda + kk + lkq);
        As[lkq + 0][lrow] = av.x; As[lkq + 1][lrow] = av.y;
        As[lkq + 2][lrow] = av.z; As[lkq + 3][lrow] = av.w;
        float4 bv = *(const float4*)(B + (size_t)(kk + bk) * ldb + bn);
        *(float4*)&Bs[bk][bn] = bv;
        __syncthreads();
        #pragma unroll
        for (int k = 0; k < 8; k++) {
            float4 a0 = *(float4*)&As[k][ty * 8];
            float4 a1 = *(float4*)&As[k][ty * 8 + 4];
            float4 b0 = *(float4*)&Bs[k][tx * 8];
            float4 b1 = *(float4*)&Bs[k][tx * 8 + 4];
            ull aa[8] = {pack2(a0.x,a0.x), pack2(a0.y,a0.y), pack2(a0.z,a0.z), pack2(a0.w,a0.w),
                         pack2(a1.x,a1.x), pack2(a1.y,a1.y), pack2(a1.z,a1.z), pack2(a1.w,a1.w)};
            ull bb[4] = {pack2(b0.x,b0.y), pack2(b0.z,b0.w), pack2(b1.x,b1.y), pack2(b1.z,b1.w)};
            #pragma unroll
            for (int i = 0; i < 8; i++)
                #pragma unroll
                for (int j = 0; j < 4; j++)
                    ffma2(acc[i][j], aa[i], bb[j]);
        }
        __syncthreads();
    }
    #pragma unroll
    for (int i = 0; i < 8; i++) {
        int row = m0 + ty * 8 + i;
        if (row >= M) continue;
        #pragma unroll
        for (int j = 0; j < 4; j++) {
            float2 v = unpack2(acc[i][j]);
            int col = tx * 8 + 2 * j;
            float c0 = v.x + bias[col];
            float c1 = v.y + bias[col + 1];
            if (act == 1) { c0 = fmaxf(c0, 0.f); c1 = fmaxf(c1, 0.f); }
            C[(size_t)row * ldc + col]     = c0;
            C[(size_t)row * ldc + col + 1] = c1;
        }
    }
}

// xe = relu(x @ Wn + bn)
__global__ __launch_bounds__(256)
void xe_gemm_k(const float* __restrict__ x, const float* __restrict__ Wn,
               const float* __restrict__ bn, int M) {
    gemm_body(x, M, S, S, Wn, S, bn, g_xe, S, 1);
}

// ZH half: g_ZH[:, half*128 : +128] = g_pxe @ g_Wcat[:, half] + g_bcat[half]
__global__ __launch_bounds__(256)
void zh_gemm_k(int half, int M) {
    gemm_body(g_pxe, M, S, S, g_Wcat + half * S, 2 * S,
              g_bcat + half * S, g_ZH + half * S, 2 * S, 0);
}

// ---------------- self-loop init + edge scatter -------------------------------
__global__ void selfloop_k(int n) {
    int idx = blockIdx.x * blockDim.x + threadIdx.x;
    if (idx < n * S) {
        int row = idx >> 7;
        float di = g_dinv[row];
        g_pxe[idx] = di * di * g_xe[idx];
    }
}

__global__ void scatter_k(int E) {
    int e = blockIdx.x * 8 + (threadIdx.x >> 5);
    if (e >= E) return;
    int lane = threadIdx.x & 31;
    int s = 0, d = 0; float c = 0.f;
    if (lane == 0) {
        s = g_src[e];
        d = g_dst[e];
        c = g_dinv[s] * g_dinv[d];
    }
    s = __shfl_sync(0xffffffffu, s, 0);
    d = __shfl_sync(0xffffffffu, d, 0);
    c = __shfl_sync(0xffffffffu, c, 0);
    float4 v = *((const float4*)(g_xe + (size_t)s * S) + lane);
    float* p = g_pxe + (size_t)d * S + lane * 4;
    atomicAdd(p + 0, v.x * c);
    atomicAdd(p + 1, v.y * c);
    atomicAdd(p + 2, v.z * c);
    atomicAdd(p + 3, v.w * c);
}

// ---------------- node epilogue: a = H.w0, b = H.w1 ---------------------------
__global__ void node_epi_k(const float* __restrict__ Wout, int n) {
    int node = blockIdx.x * 8 + (threadIdx.x >> 5);
    if (node >= n) return;
    int lane = threadIdx.x & 31;
    const float* zh = g_ZH + (size_t)node * 2 * S;
    float4 z4 = *(const float4*)(zh + lane * 4);
    float4 h4 = *(const float4*)(zh + S + lane * 4);
    float av = 0.f, bv = 0.f;
    float zp[4] = {z4.x, z4.y, z4.z, z4.w};
    float hp[4] = {h4.x, h4.y, h4.z, h4.w};
    #pragma unroll
    for (int q = 0; q < 4; q++) {
        float Z  = 1.f / (1.f + expf(-zp[q]));
        float Ht = tanhf(hp[q]);
        float H  = (1.f - Z) * Ht;
        int j = lane * 4 + q;
        av += H * Wout[j];
        bv += H * Wout[S + j];
    }
    #pragma unroll
    for (int off = 16; off; off >>= 1) {
        av += __shfl_down_sync(0xffffffffu, av, off);
        bv += __shfl_down_sync(0xffffffffu, bv, off);
    }
    if (lane == 0) { g_as[node] = av; g_bs[node] = bv; }
}

// ---------------- fused edge GEMM + reduce ------------------------------------
// out[e] = relu(EA[e]@We + be) . w2  +  a[src] + b[dst] + bout
__global__ __launch_bounds__(256)
void edge_out_k(const float* __restrict__ EA, const float* __restrict__ We,
                const float* __restrict__ be, const float* __restrict__ Wout,
                const float* __restrict__ bout,
                float* __restrict__ out, int E) {
    __shared__ float As[8][128];
    __shared__ float Bs[8][128];
    __shared__ float red[128][17];
    int tid = threadIdx.x;
    int tx = tid & 15, ty = tid >> 4;
    int m0 = blockIdx.x * 128;
    int lrow = tid >> 1;
    int lkq  = (tid & 1) * 4;
    int bk = tid >> 5;
    int bn = (tid & 31) * 4;

    ull acc[8][4];
    #pragma unroll
    for (int i = 0; i < 8; i++)
        #pragma unroll
        for (int j = 0; j < 4; j++) acc[i][j] = 0ull;

    for (int kk = 0; kk < 64; kk += 8) {
        float4 av = make_float4(0.f, 0.f, 0.f, 0.f);
        int arow = m0 + lrow;
        if (arow < E) av = *(const float4*)(EA + (size_t)arow * 64 + kk + lkq);
        As[lkq + 0][lrow] = av.x; As[lkq + 1][lrow] = av.y;
        As[lkq + 2][lrow] = av.z; As[lkq + 3][lrow] = av.w;
        float4 bv = *(const float4*)(We + (size_t)(kk + bk) * 128 + bn);
        *(float4*)&Bs[bk][bn] = bv;
        __syncthreads();
        #pragma unroll
        for (int k = 0; k < 8; k++) {
            float4 a0 = *(float4*)&As[k][ty * 8];
            float4 a1 = *(float4*)&As[k][ty * 8 + 4];
            float4 b0 = *(float4*)&Bs[k][tx * 8];
            float4 b1 = *(float4*)&Bs[k][tx * 8 + 4];
            ull aa[8] = {pack2(a0.x,a0.x), pack2(a0.y,a0.y), pack2(a0.z,a0.z), pack2(a0.w,a0.w),
                         pack2(a1.x,a1.x), pack2(a1.y,a1.y), pack2(a1.z,a1.z), pack2(a1.w,a1.w)};
            ull bb[4] = {pack2(b0.x,b0.y), pack2(b0.z,b0.w), pack2(b1.x,b1.y), pack2(b1.z,b1.w)};
            #pragma unroll
            for (int i = 0; i < 8; i++)
                #pragma unroll
                for (int j = 0; j < 4; j++)
                    ffma2(acc[i][j], aa[i], bb[j]);
        }
        __syncthreads();
    }
    const float* w2 = Wout + 2 * S;
    #pragma unroll
    for (int i = 0; i < 8; i++) {
        int row = ty * 8 + i;
        float p = 0.f;
        #pragma unroll
        for (int j = 0; j < 4; j++) {
            float2 v = unpack2(acc[i][j]);
            int col = tx * 8 + 2 * j;
            float c0 = fmaxf(v.x + be[col],     0.f);
            float c1 = fmaxf(v.y + be[col + 1], 0.f);
            p += c0 * w2[col] + c1 * w2[col + 1];
        }
        red[row][tx] = p;
    }
    __syncthreads();
    if (tid < 128) {
        float s = 0.f;
        #pragma unroll
        for (int t = 0; t < 16; t++) s += red[tid][t];
        int e = m0 + tid;
        if (e < E) {
            out[e] = s + g_as[g_src[e]] + g_bs[g_dst[e]] + bout[0];
        }
    }
}

// ---------------- launch: kernel launches ONLY --------------------------------
extern "C" void kernel_launch(void* const* d_in, const int* in_sizes, int n_in,
                              void* d_out, int out_size) {
    const float* x    = (const float*)d_in[0];
    const int*   ei32 = (const int*)d_in[1];   // int32 OR int64 (detected on-device)
    const float* ea   = (const float*)d_in[2];
    const float* Wn   = (const float*)d_in[3];
    const float* bn   = (const float*)d_in[4];
    const float* We   = (const float*)d_in[5];
    const float* be   = (const float*)d_in[6];
    const float* Wzc  = (const float*)d_in[7];
    const float* bzc  = (const float*)d_in[8];
    const float* Wzl  = (const float*)d_in[9];
    const float* bzl  = (const float*)d_in[10];
    // d_in[11..14] = Wrc, brc, Wrl, brl  -- dead (H=0 makes R unused)
    const float* Whc  = (const float*)d_in[15];
    const float* bhc  = (const float*)d_in[16];
    const float* Whl  = (const float*)d_in[17];
    const float* bhl  = (const float*)d_in[18];
    const float* Wout = (const float*)d_in[19];
    const float* bout = (const float*)d_in[20];
    float* out = (float*)d_out;

    int nN = in_sizes[0] / S;      // 50000
    int nE = in_sizes[2] / 64;     // 800000

    // 0) detect edge-index dtype, decode to int32 src/dst
    ei_detect_k<<<1, 256>>>(ei32, nE);
    ei_decode_k<<<(nE + 255) / 256, 256>>>(ei32, nE, nN);

    // 1) fold gate weights (tiny)
    prep_w_k<<<128, 256>>>(Wzc, Wzl, Whc, Whl);
    prep_b_k<<<1, 256>>>(bzc, Wzl, bzl, bhc, Whl, bhl);

    // 2) degree / norm
    deg_init_k<<<(nN + 255) / 256, 256>>>(nN);
    deg_acc_k<<<(nE + 255) / 256, 256>>>(nE);
    dinv_k<<<(nN + 255) / 256, 256>>>(nN);

    // 3) xe = relu(x @ Wn + bn)
    xe_gemm_k<<<(nN + 127) / 128, 256>>>(x, Wn, bn, nN);

    // 4) pxe = D^-1/2 (A + I) D^-1/2 xe
    selfloop_k<<<(nN * S + 255) / 256, 256>>>(nN);
    scatter_k<<<(nE + 7) / 8, 256>>>(nE);

    // 5) ZH pre-activations: pxe @ [Wz2 | Wh2] + [bz2 | bh2]
    zh_gemm_k<<<(nN + 127) / 128, 256>>>(0, nN);
    zh_gemm_k<<<(nN + 127) / 128, 256>>>(1, nN);

    // 6) per-node scalars a = H.w0, b = H.w1
    node_epi_k<<<(nN + 7) / 8, 256>>>(Wout, nN);

    // 7) fused edge GEMM + reduction + gather
    edge_out_k<<<(nE + 127) / 128, 256>>>(ea, We, be, Wout, bout, out, nE);
}

// round 14
// speedup vs baseline: 1.0910x; 1.0910x over previous
#include <cuda_runtime.h>
#include <math.h>

// Problem constants (fixed by the dataset)
#define NN 50000
#define NE 800000
#define S  128

typedef unsigned long long ull;

// ---------------- scratch (device globals; referenced directly) ---------------
__device__ float g_xe [(size_t)NN * S];      // relu(x@Wn+bn)
__device__ float g_pxe[(size_t)NN * S];      // normalized-adjacency propagated xe
__device__ float g_deg [NN];
__device__ float g_dinv[NN];
__device__ float g_as[NN];                   // H . w0
__device__ float g_bs[NN];                   // H . w1
__device__ float g_Wcat[S * 2 * S];          // [128][256] = [Wzc@Wzl_top | Whc@Whl_top]
__device__ float g_bcat[2 * S];
__device__ int   g_src[NE];                  // decoded edge sources
__device__ int   g_dst[NE];                  // decoded edge destinations
__device__ int   g_eimode;                   // 1 = int64 input layout, 0 = int32

// ---------------- packed f32x2 helpers --------------------------------------
__device__ __forceinline__ ull pack2(float x, float y) {
    ull r; asm("mov.b64 %0, {%1,%2};" : "=l"(r) : "f"(x), "f"(y)); return r;
}
__device__ __forceinline__ void ffma2(ull &d, ull a, ull b) {
    asm("fma.rn.f32x2 %0, %1, %2, %0;" : "+l"(d) : "l"(a), "l"(b));
}
__device__ __forceinline__ float2 unpack2(ull v) {
    float2 f; asm("mov.b64 {%0,%1}, %2;" : "=f"(f.x), "=f"(f.y) : "l"(v)); return f;
}

// ---------------- edge-index dtype detection + decode -------------------------
// int64 entries (values < 2^31, little-endian): odd 32-bit words are all zero.
__global__ void ei_detect_k(const int* __restrict__ ei32, int E) {
    __shared__ int s_nonzero;
    if (threadIdx.x == 0) s_nonzero = 0;
    __syncthreads();
    int nsamp = 4096;
    if (nsamp > E) nsamp = E;
    int stride = (2 * E) / nsamp;
    if (stride < 1) stride = 1;
    int bad = 0;
    for (int k = threadIdx.x; k < nsamp; k += blockDim.x) {
        size_t entry = (size_t)k * stride;
        if (ei32[2 * entry + 1] != 0) bad = 1;
    }
    if (bad) atomicOr(&s_nonzero, 1);
    __syncthreads();
    if (threadIdx.x == 0) g_eimode = (s_nonzero == 0) ? 1 : 0;
}

__global__ void ei_decode_k(const int* __restrict__ ei32, int E, int n) {
    int e = blockIdx.x * blockDim.x + threadIdx.x;
    if (e >= E) return;
    int s, d;
    if (g_eimode) {
        s = ei32[2 * (size_t)e];
        d = ei32[2 * ((size_t)E + e)];
    } else {
        s = ei32[e];
        d = ei32[(size_t)E + e];
    }
    s = min(max(s, 0), n - 1);
    d = min(max(d, 0), n - 1);
    g_src[e] = s;
    g_dst[e] = d;
}

// ---------------- weight folding --------------------------------------------
__global__ void prep_w_k(const float* __restrict__ Wzc, const float* __restrict__ Wzl,
                         const float* __restrict__ Whc, const float* __restrict__ Whl) {
    int k = blockIdx.x;
    int n = threadIdx.x;
    const float* Wc; const float* Wl; int nn;
    if (n < S) { Wc = Wzc + (size_t)k * S; Wl = Wzl; nn = n; }
    else       { Wc = Whc + (size_t)k * S; Wl = Whl; nn = n - S; }
    float s = 0.f;
    #pragma unroll 8
    for (int i = 0; i < S; i++) s += Wc[i] * Wl[(size_t)i * S + nn];
    g_Wcat[(size_t)k * 2 * S + n] = s;
}

__global__ void prep_b_k(const float* __restrict__ bzc, const float* __restrict__ Wzl,
                         const float* __restrict__ bzl,
                         const float* __restrict__ bhc, const float* __restrict__ Whl,
                         const float* __restrict__ bhl) {
    int n = threadIdx.x;
    const float* bc; const float* Wl; const float* bl; int nn;
    if (n < S) { bc = bzc; Wl = Wzl; bl = bzl; nn = n; }
    else       { bc = bhc; Wl = Whl; bl = bhl; nn = n - S; }
    float s = 0.f;
    #pragma unroll 8
    for (int i = 0; i < S; i++) s += bc[i] * Wl[(size_t)i * S + nn];
    g_bcat[n] = s + bl[nn];
}

// ---------------- degree / norm ----------------------------------------------
__global__ void deg_init_k(int n) {
    int i = blockIdx.x * blockDim.x + threadIdx.x;
    if (i < n) g_deg[i] = 1.0f;
}
__global__ void deg_acc_k(int E) {
    int e = blockIdx.x * blockDim.x + threadIdx.x;
    if (e < E) atomicAdd(&g_deg[g_dst[e]], 1.0f);
}
__global__ void dinv_k(int n) {
    int i = blockIdx.x * blockDim.x + threadIdx.x;
    if (i < n) g_dinv[i] = rsqrtf(g_deg[i]);
}

// ---------------- double-buffered fp32 GEMM body ------------------------------
// C = act(A[M,K] @ B[K,128] + bias). BM=128, BN=128, BK=8, 256 thr, 8x8 tiles.
// 2-stage smem pipeline: prefetch tile k+1 while computing tile k; 1 sync/iter.
__device__ __forceinline__
void gemm_body_db(const float* __restrict__ A, int M, int K, int lda,
                  const float* __restrict__ B, int ldb,
                  const float* __restrict__ bias,
                  float* __restrict__ C, int ldc, int act) {
    __shared__ float As[2][8][128];
    __shared__ float Bs[2][8][128];
    int tid = threadIdx.x;
    int tx = tid & 15, ty = tid >> 4;
    int m0 = blockIdx.x * 128;
    int lrow = tid >> 1;
    int lkq  = (tid & 1) * 4;
    int bk = tid >> 5;
    int bn = (tid & 31) * 4;
    int arow = m0 + lrow;
    int nsteps = K >> 3;

    ull acc[8][4];
    #pragma unroll
    for (int i = 0; i < 8; i++)
        #pragma unroll
        for (int j = 0; j < 4; j++) acc[i][j] = 0ull;

    // prologue: fetch tile 0
    float4 av = make_float4(0.f, 0.f, 0.f, 0.f);
    if (arow < M) av = *(const float4*)(A + (size_t)arow * lda + lkq);
    float4 bv = *(const float4*)(B + (size_t)bk * ldb + bn);
    As[0][lkq + 0][lrow] = av.x; As[0][lkq + 1][lrow] = av.y;
    As[0][lkq + 2][lrow] = av.z; As[0][lkq + 3][lrow] = av.w;
    *(float4*)&Bs[0][bk][bn] = bv;
    __syncthreads();

    int cur = 0;
    for (int s = 0; s < nsteps; s++) {
        // prefetch next tile into registers (overlaps with compute below)
        if (s + 1 < nsteps) {
            int kk = (s + 1) << 3;
            av = make_float4(0.f, 0.f, 0.f, 0.f);
            if (arow < M) av = *(const float4*)(A + (size_t)arow * lda + kk + lkq);
            bv = *(const float4*)(B + (size_t)(kk + bk) * ldb + bn);
        }
        #pragma unroll
        for (int k = 0; k < 8; k++) {
            float4 a0 = *(float4*)&As[cur][k][ty * 8];
            float4 a1 = *(float4*)&As[cur][k][ty * 8 + 4];
            float4 b0 = *(float4*)&Bs[cur][k][tx * 8];
            float4 b1 = *(float4*)&Bs[cur][k][tx * 8 + 4];
            ull aa[8] = {pack2(a0.x,a0.x), pack2(a0.y,a0.y), pack2(a0.z,a0.z), pack2(a0.w,a0.w),
                         pack2(a1.x,a1.x), pack2(a1.y,a1.y), pack2(a1.z,a1.z), pack2(a1.w,a1.w)};
            ull bb[4] = {pack2(b0.x,b0.y), pack2(b0.z,b0.w), pack2(b1.x,b1.y), pack2(b1.z,b1.w)};
            #pragma unroll
            for (int i = 0; i < 8; i++)
                #pragma unroll
                for (int j = 0; j < 4; j++)
                    ffma2(acc[i][j], aa[i], bb[j]);
        }
        if (s + 1 < nsteps) {
            int nxt = cur ^ 1;
            As[nxt][lkq + 0][lrow] = av.x; As[nxt][lkq + 1][lrow] = av.y;
            As[nxt][lkq + 2][lrow] = av.z; As[nxt][lkq + 3][lrow] = av.w;
            *(float4*)&Bs[nxt][bk][bn] = bv;
            __syncthreads();
            cur = nxt;
        }
    }
    #pragma unroll
    for (int i = 0; i < 8; i++) {
        int row = m0 + ty * 8 + i;
        if (row >= M) continue;
        #pragma unroll
        for (int j = 0; j < 4; j++) {
            float2 v = unpack2(acc[i][j]);
            int col = tx * 8 + 2 * j;
            float c0 = v.x + bias[col];
            float c1 = v.y + bias[col + 1];
            if (act == 1) { c0 = fmaxf(c0, 0.f); c1 = fmaxf(c1, 0.f); }
            C[(size_t)row * ldc + col]     = c0;
            C[(size_t)row * ldc + col + 1] = c1;
        }
    }
}

// xe = relu(x @ Wn + bn)
__global__ __launch_bounds__(256)
void xe_gemm_k(const float* __restrict__ x, const float* __restrict__ Wn,
               const float* __restrict__ bn, int M) {
    gemm_body_db(x, M, S, S, Wn, S, bn, g_xe, S, 1);
}

// ---------------- fused ZH GEMM + GRU activation + w0/w1 dot ------------------
// For each node row: z = pxe@Wcat[:,0:128]+bcat[0:128], h = pxe@Wcat[:,128:256]+bcat[128:]
// H = (1-sigmoid(z))*tanh(h);  g_as = H.w0, g_bs = H.w1.  Never materializes ZH.
__global__ __launch_bounds__(256)
void zhab_gemm_k(const float* __restrict__ Wout, int M) {
    __shared__ float As[8][128];
    __shared__ float Bs[2][8][128];
    __shared__ float red_a[128][17];
    __shared__ float red_b[128][17];
    int tid = threadIdx.x;
    int tx = tid & 15, ty = tid >> 4;
    int m0 = blockIdx.x * 128;
    int lrow = tid >> 1;
    int lkq  = (tid & 1) * 4;
    int bk = tid >> 5;
    int bn = (tid & 31) * 4;
    int arow = m0 + lrow;

    ull acc[2][8][4];
    #pragma unroll
    for (int h = 0; h < 2; h++)
        #pragma unroll
        for (int i = 0; i < 8; i++)
            #pragma unroll
            for (int j = 0; j < 4; j++) acc[h][i][j] = 0ull;

    for (int kk = 0; kk < S; kk += 8) {
        float4 av = make_float4(0.f, 0.f, 0.f, 0.f);
        if (arow < M) av = *(const float4*)(g_pxe + (size_t)arow * S + kk + lkq);
        As[lkq + 0][lrow] = av.x; As[lkq + 1][lrow] = av.y;
        As[lkq + 2][lrow] = av.z; As[lkq + 3][lrow] = av.w;
        #pragma unroll
        for (int h = 0; h < 2; h++) {
            float4 bv = *(const float4*)(g_Wcat + (size_t)(kk + bk) * 2 * S + h * S + bn);
            *(float4*)&Bs[h][bk][bn] = bv;
        }
        __syncthreads();
        #pragma unroll
        for (int k = 0; k < 8; k++) {
            float4 a0 = *(float4*)&As[k][ty * 8];
            float4 a1 = *(float4*)&As[k][ty * 8 + 4];
            ull aa[8] = {pack2(a0.x,a0.x), pack2(a0.y,a0.y), pack2(a0.z,a0.z), pack2(a0.w,a0.w),
                         pack2(a1.x,a1.x), pack2(a1.y,a1.y), pack2(a1.z,a1.z), pack2(a1.w,a1.w)};
            #pragma unroll
            for (int h = 0; h < 2; h++) {
                float4 b0 = *(float4*)&Bs[h][k][tx * 8];
                float4 b1 = *(float4*)&Bs[h][k][tx * 8 + 4];
                ull bb[4] = {pack2(b0.x,b0.y), pack2(b0.z,b0.w), pack2(b1.x,b1.y), pack2(b1.z,b1.w)};
                #pragma unroll
                for (int i = 0; i < 8; i++)
                    #pragma unroll
                    for (int j = 0; j < 4; j++)
                        ffma2(acc[h][i][j], aa[i], bb[j]);
            }
        }
        __syncthreads();
    }

    // epilogue: GRU activation + dot with w0/w1, reduce 16 tx-threads per row
    #pragma unroll
    for (int i = 0; i < 8; i++) {
        float pa = 0.f, pb = 0.f;
        #pragma unroll
        for (int j = 0; j < 4; j++) {
            float2 zv = unpack2(acc[0][i][j]);
            float2 hv = unpack2(acc[1][i][j]);
            int col = tx * 8 + 2 * j;
            #pragma unroll
            for (int q = 0; q < 2; q++) {
                float z = (q ? zv.y : zv.x) + g_bcat[col + q];
                float h = (q ? hv.y : hv.x) + g_bcat[S + col + q];
                float Z  = 1.f / (1.f + expf(-z));
                float Ht = tanhf(h);
                float Hv = (1.f - Z) * Ht;
                pa += Hv * Wout[col + q];
                pb += Hv * Wout[S + col + q];
            }
        }
        int row = ty * 8 + i;
        red_a[row][tx] = pa;
        red_b[row][tx] = pb;
    }
    __syncthreads();
    if (tid < 128) {
        float sa = 0.f, sb = 0.f;
        #pragma unroll
        for (int t = 0; t < 16; t++) { sa += red_a[tid][t]; sb += red_b[tid][t]; }
        int node = m0 + tid;
        if (node < M) { g_as[node] = sa; g_bs[node] = sb; }
    }
}

// ---------------- self-loop init + edge scatter -------------------------------
__global__ void selfloop_k(int n) {
    int idx = blockIdx.x * blockDim.x + threadIdx.x;
    if (idx < n * S) {
        int row = idx >> 7;
        float di = g_dinv[row];
        g_pxe[idx] = di * di * g_xe[idx];
    }
}

__global__ void scatter_k(int E) {
    int e = blockIdx.x * 8 + (threadIdx.x >> 5);
    if (e >= E) return;
    int lane = threadIdx.x & 31;
    int s = 0, d = 0; float c = 0.f;
    if (lane == 0) {
        s = g_src[e];
        d = g_dst[e];
        c = g_dinv[s] * g_dinv[d];
    }
    s = __shfl_sync(0xffffffffu, s, 0);
    d = __shfl_sync(0xffffffffu, d, 0);
    c = __shfl_sync(0xffffffffu, c, 0);
    float4 v = *((const float4*)(g_xe + (size_t)s * S) + lane);
    float* p = g_pxe + (size_t)d * S + lane * 4;
    atomicAdd(p + 0, v.x * c);
    atomicAdd(p + 1, v.y * c);
    atomicAdd(p + 2, v.z * c);
    atomicAdd(p + 3, v.w * c);
}

// ---------------- fused edge GEMM + reduce (double-buffered) ------------------
// out[e] = relu(EA[e]@We + be) . w2  +  a[src] + b[dst] + bout
__global__ __launch_bounds__(256)
void edge_out_k(const float* __restrict__ EA, const float* __restrict__ We,
                const float* __restrict__ be, const float* __restrict__ Wout,
                const float* __restrict__ bout,
                float* __restrict__ out, int E) {
    __shared__ float As[2][8][128];
    __shared__ float Bs[2][8][128];
    __shared__ float red[128][17];
    int tid = threadIdx.x;
    int tx = tid & 15, ty = tid >> 4;
    int m0 = blockIdx.x * 128;
    int lrow = tid >> 1;
    int lkq  = (tid & 1) * 4;
    int bk = tid >> 5;
    int bn = (tid & 31) * 4;
    int arow = m0 + lrow;
    const int nsteps = 8;   // K = 64

    ull acc[8][4];
    #pragma unroll
    for (int i = 0; i < 8; i++)
        #pragma unroll
        for (int j = 0; j < 4; j++) acc[i][j] = 0ull;

    float4 av = make_float4(0.f, 0.f, 0.f, 0.f);
    if (arow < E) av = *(const float4*)(EA + (size_t)arow * 64 + lkq);
    float4 bv = *(const float4*)(We + (size_t)bk * 128 + bn);
    As[0][lkq + 0][lrow] = av.x; As[0][lkq + 1][lrow] = av.y;
    As[0][lkq + 2][lrow] = av.z; As[0][lkq + 3][lrow] = av.w;
    *(float4*)&Bs[0][bk][bn] = bv;
    __syncthreads();

    int cur = 0;
    for (int s = 0; s < nsteps; s++) {
        if (s + 1 < nsteps) {
            int kk = (s + 1) << 3;
            av = make_float4(0.f, 0.f, 0.f, 0.f);
            if (arow < E) av = *(const float4*)(EA + (size_t)arow * 64 + kk + lkq);
            bv = *(const float4*)(We + (size_t)(kk + bk) * 128 + bn);
        }
        #pragma unroll
        for (int k = 0; k < 8; k++) {
            float4 a0 = *(float4*)&As[cur][k][ty * 8];
            float4 a1 = *(float4*)&As[cur][k][ty * 8 + 4];
            float4 b0 = *(float4*)&Bs[cur][k][tx * 8];
            float4 b1 = *(float4*)&Bs[cur][k][tx * 8 + 4];
            ull aa[8] = {pack2(a0.x,a0.x), pack2(a0.y,a0.y), pack2(a0.z,a0.z), pack2(a0.w,a0.w),
                         pack2(a1.x,a1.x), pack2(a1.y,a1.y), pack2(a1.z,a1.z), pack2(a1.w,a1.w)};
            ull bb[4] = {pack2(b0.x,b0.y), pack2(b0.z,b0.w), pack2(b1.x,b1.y), pack2(b1.z,b1.w)};
            #pragma unroll
            for (int i = 0; i < 8; i++)
                #pragma unroll
                for (int j = 0; j < 4; j++)
                    ffma2(acc[i][j], aa[i], bb[j]);
        }
        if (s + 1 < nsteps) {
            int nxt = cur ^ 1;
            As[nxt][lkq + 0][lrow] = av.x; As[nxt][lkq + 1][lrow] = av.y;
            As[nxt][lkq + 2][lrow] = av.z; As[nxt][lkq + 3][lrow] = av.w;
            *(float4*)&Bs[nxt][bk][bn] = bv;
            __syncthreads();
            cur = nxt;
        }
    }
    const float* w2 = Wout + 2 * S;
    #pragma unroll
    for (int i = 0; i < 8; i++) {
        int row = ty * 8 + i;
        float p = 0.f;
        #pragma unroll
        for (int j = 0; j < 4; j++) {
            float2 v = unpack2(acc[i][j]);
            int col = tx * 8 + 2 * j;
            float c0 = fmaxf(v.x + be[col],     0.f);
            float c1 = fmaxf(v.y + be[col + 1], 0.f);
            p += c0 * w2[col] + c1 * w2[col + 1];
        }
        red[row][tx] = p;
    }
    __syncthreads();
    if (tid < 128) {
        float s = 0.f;
        #pragma unroll
        for (int t = 0; t < 16; t++) s += red[tid][t];
        int e = m0 + tid;
        if (e < E) {
            out[e] = s + g_as[g_src[e]] + g_bs[g_dst[e]] + bout[0];
        }
    }
}

// ---------------- launch: kernel launches ONLY --------------------------------
extern "C" void kernel_launch(void* const* d_in, const int* in_sizes, int n_in,
                              void* d_out, int out_size) {
    const float* x    = (const float*)d_in[0];
    const int*   ei32 = (const int*)d_in[1];   // int32 OR int64 (detected on-device)
    const float* ea   = (const float*)d_in[2];
    const float* Wn   = (const float*)d_in[3];
    const float* bn   = (const float*)d_in[4];
    const float* We   = (const float*)d_in[5];
    const float* be   = (const float*)d_in[6];
    const float* Wzc  = (const float*)d_in[7];
    const float* bzc  = (const float*)d_in[8];
    const float* Wzl  = (const float*)d_in[9];
    const float* bzl  = (const float*)d_in[10];
    // d_in[11..14] = Wrc, brc, Wrl, brl  -- dead (H=0 makes R unused)
    const float* Whc  = (const float*)d_in[15];
    const float* bhc  = (const float*)d_in[16];
    const float* Whl  = (const float*)d_in[17];
    const float* bhl  = (const float*)d_in[18];
    const float* Wout = (const float*)d_in[19];
    const float* bout = (const float*)d_in[20];
    float* out = (float*)d_out;

    int nN = in_sizes[0] / S;      // 50000
    int nE = in_sizes[2] / 64;     // 800000

    // 0) detect edge-index dtype, decode to int32 src/dst
    ei_detect_k<<<1, 256>>>(ei32, nE);
    ei_decode_k<<<(nE + 255) / 256, 256>>>(ei32, nE, nN);

    // 1) fold gate weights (tiny)
    prep_w_k<<<128, 256>>>(Wzc, Wzl, Whc, Whl);
    prep_b_k<<<1, 256>>>(bzc, Wzl, bzl, bhc, Whl, bhl);

    // 2) degree / norm
    deg_init_k<<<(nN + 255) / 256, 256>>>(nN);
    deg_acc_k<<<(nE + 255) / 256, 256>>>(nE);
    dinv_k<<<(nN + 255) / 256, 256>>>(nN);

    // 3) xe = relu(x @ Wn + bn)
    xe_gemm_k<<<(nN + 127) / 128, 256>>>(x, Wn, bn, nN);

    // 4) pxe = D^-1/2 (A + I) D^-1/2 xe
    selfloop_k<<<(nN * S + 255) / 256, 256>>>(nN);
    scatter_k<<<(nE + 7) / 8, 256>>>(nE);

    // 5+6) fused: both gate GEMMs + GRU activation + w0/w1 dots -> g_as, g_bs
    zhab_gemm_k<<<(nN + 127) / 128, 256>>>(Wout, nN);

    // 7) fused edge GEMM + reduction + gather
    edge_out_k<<<(nE + 127) / 128, 256>>>(ea, We, be, Wout, bout, out, nE);
}

// round 15
// speedup vs baseline: 1.3143x; 1.2047x over previous
#include <cuda_runtime.h>
#include <math.h>

// Problem constants (fixed by the dataset)
#define NN 50000
#define NE 800000
#define S  128

typedef unsigned long long ull;

// ---------------- scratch (device globals; referenced directly) ---------------
__device__ float g_xe [(size_t)NN * S];      // relu(x@Wn+bn)
__device__ float g_pxe[(size_t)NN * S];      // normalized-adjacency propagated xe
__device__ float g_deg [NN];
__device__ float g_dinv[NN];
__device__ float g_as[NN];                   // H . w0
__device__ float g_bs[NN];                   // H . w1
__device__ float g_Wcat[S * 2 * S];          // [128][256] = [Wzc@Wzl_top | Whc@Whl_top]
__device__ float g_bcat[2 * S];
__device__ int   g_src[NE];                  // decoded edge sources
__device__ int   g_dst[NE];                  // decoded edge destinations
__device__ int   g_eimode;                   // 1 = int64 input layout, 0 = int32

// ---------------- packed f32x2 helpers --------------------------------------
__device__ __forceinline__ ull pack2(float x, float y) {
    ull r; asm("mov.b64 %0, {%1,%2};" : "=l"(r) : "f"(x), "f"(y)); return r;
}
__device__ __forceinline__ void ffma2(ull &d, ull a, ull b) {
    asm("fma.rn.f32x2 %0, %1, %2, %0;" : "+l"(d) : "l"(a), "l"(b));
}
__device__ __forceinline__ float2 unpack2(ull v) {
    float2 f; asm("mov.b64 {%0,%1}, %2;" : "=f"(f.x), "=f"(f.y) : "l"(v)); return f;
}

// ---------------- edge-index dtype detection ----------------------------------
// int64 entries (values < 2^31, little-endian): odd 32-bit words are all zero.
__global__ void ei_detect_k(const int* __restrict__ ei32, int E) {
    __shared__ int s_nonzero;
    if (threadIdx.x == 0) s_nonzero = 0;
    __syncthreads();
    int nsamp = 4096;
    if (nsamp > E) nsamp = E;
    int stride = (2 * E) / nsamp;
    if (stride < 1) stride = 1;
    int bad = 0;
    for (int k = threadIdx.x; k < nsamp; k += blockDim.x) {
        size_t entry = (size_t)k * stride;
        if (ei32[2 * entry + 1] != 0) bad = 1;
    }
    if (bad) atomicOr(&s_nonzero, 1);
    __syncthreads();
    if (threadIdx.x == 0) g_eimode = (s_nonzero == 0) ? 1 : 0;
}

// decode + degree accumulation fused (g_deg pre-initialized to 1.0 by deg_init_k)
__global__ void ei_decode_k(const int* __restrict__ ei32, int E, int n) {
    int e = blockIdx.x * blockDim.x + threadIdx.x;
    if (e >= E) return;
    int s, d;
    if (g_eimode) {
        s = ei32[2 * (size_t)e];
        d = ei32[2 * ((size_t)E + e)];
    } else {
        s = ei32[e];
        d = ei32[(size_t)E + e];
    }
    s = min(max(s, 0), n - 1);
    d = min(max(d, 0), n - 1);
    g_src[e] = s;
    g_dst[e] = d;
    atomicAdd(&g_deg[d], 1.0f);
}

// ---------------- weight folding --------------------------------------------
__global__ void prep_w_k(const float* __restrict__ Wzc, const float* __restrict__ Wzl,
                         const float* __restrict__ Whc, const float* __restrict__ Whl) {
    int k = blockIdx.x;
    int n = threadIdx.x;
    const float* Wc; const float* Wl; int nn;
    if (n < S) { Wc = Wzc + (size_t)k * S; Wl = Wzl; nn = n; }
    else       { Wc = Whc + (size_t)k * S; Wl = Whl; nn = n - S; }
    float s = 0.f;
    #pragma unroll 8
    for (int i = 0; i < S; i++) s += Wc[i] * Wl[(size_t)i * S + nn];
    g_Wcat[(size_t)k * 2 * S + n] = s;
}

// parallel bias fold: one block per output column, 128-thread reduction
__global__ void prep_b_k(const float* __restrict__ bzc, const float* __restrict__ Wzl,
                         const float* __restrict__ bzl,
                         const float* __restrict__ bhc, const float* __restrict__ Whl,
                         const float* __restrict__ bhl) {
    __shared__ float sred[4];
    int n = blockIdx.x;          // 0..255
    int t = threadIdx.x;         // 0..127
    const float* bc; const float* Wl; const float* bl; int nn;
    if (n < S) { bc = bzc; Wl = Wzl; bl = bzl; nn = n; }
    else       { bc = bhc; Wl = Whl; bl = bhl; nn = n - S; }
    float v = bc[t] * Wl[(size_t)t * S + nn];
    #pragma unroll
    for (int off = 16; off; off >>= 1) v += __shfl_down_sync(0xffffffffu, v, off);
    if ((t & 31) == 0) sred[t >> 5] = v;
    __syncthreads();
    if (t == 0) g_bcat[n] = sred[0] + sred[1] + sred[2] + sred[3] + bl[nn];
}

// ---------------- degree / norm ----------------------------------------------
__global__ void deg_init_k(int n) {
    int i = blockIdx.x * blockDim.x + threadIdx.x;
    if (i < n) g_deg[i] = 1.0f;
}
__global__ void dinv_k(int n) {
    int i = blockIdx.x * blockDim.x + threadIdx.x;
    if (i < n) g_dinv[i] = rsqrtf(g_deg[i]);
}

// ---------------- xe GEMM (double-buffered) + self-loop pxe init -------------
// g_xe = relu(x@Wn+bn);  g_pxe = dinv[row]^2 * g_xe  (self-loop term)
__global__ __launch_bounds__(256)
void xe_gemm_k(const float* __restrict__ x, const float* __restrict__ Wn,
               const float* __restrict__ bn, int M) {
    __shared__ float As[2][8][128];
    __shared__ float Bs[2][8][128];
    int tid = threadIdx.x;
    int tx = tid & 15, ty = tid >> 4;
    int m0 = blockIdx.x * 128;
    int lrow = tid >> 1;
    int lkq  = (tid & 1) * 4;
    int bk = tid >> 5;
    int bn_ = (tid & 31) * 4;
    int arow = m0 + lrow;
    const int nsteps = S >> 3;   // 16

    ull acc[8][4];
    #pragma unroll
    for (int i = 0; i < 8; i++)
        #pragma unroll
        for (int j = 0; j < 4; j++) acc[i][j] = 0ull;

    float4 av = make_float4(0.f, 0.f, 0.f, 0.f);
    if (arow < M) av = *(const float4*)(x + (size_t)arow * S + lkq);
    float4 bv = *(const float4*)(Wn + (size_t)bk * S + bn_);
    As[0][lkq + 0][lrow] = av.x; As[0][lkq + 1][lrow] = av.y;
    As[0][lkq + 2][lrow] = av.z; As[0][lkq + 3][lrow] = av.w;
    *(float4*)&Bs[0][bk][bn_] = bv;
    __syncthreads();

    int cur = 0;
    for (int s = 0; s < nsteps; s++) {
        if (s + 1 < nsteps) {
            int kk = (s + 1) << 3;
            av = make_float4(0.f, 0.f, 0.f, 0.f);
            if (arow < M) av = *(const float4*)(x + (size_t)arow * S + kk + lkq);
            bv = *(const float4*)(Wn + (size_t)(kk + bk) * S + bn_);
        }
        #pragma unroll
        for (int k = 0; k < 8; k++) {
            float4 a0 = *(float4*)&As[cur][k][ty * 8];
            float4 a1 = *(float4*)&As[cur][k][ty * 8 + 4];
            float4 b0 = *(float4*)&Bs[cur][k][tx * 8];
            float4 b1 = *(float4*)&Bs[cur][k][tx * 8 + 4];
            ull aa[8] = {pack2(a0.x,a0.x), pack2(a0.y,a0.y), pack2(a0.z,a0.z), pack2(a0.w,a0.w),
                         pack2(a1.x,a1.x), pack2(a1.y,a1.y), pack2(a1.z,a1.z), pack2(a1.w,a1.w)};
            ull bb[4] = {pack2(b0.x,b0.y), pack2(b0.z,b0.w), pack2(b1.x,b1.y), pack2(b1.z,b1.w)};
            #pragma unroll
            for (int i = 0; i < 8; i++)
                #pragma unroll
                for (int j = 0; j < 4; j++)
                    ffma2(acc[i][j], aa[i], bb[j]);
        }
        if (s + 1 < nsteps) {
            int nxt = cur ^ 1;
            As[nxt][lkq + 0][lrow] = av.x; As[nxt][lkq + 1][lrow] = av.y;
            As[nxt][lkq + 2][lrow] = av.z; As[nxt][lkq + 3][lrow] = av.w;
            *(float4*)&Bs[nxt][bk][bn_] = bv;
            __syncthreads();
            cur = nxt;
        }
    }
    #pragma unroll
    for (int i = 0; i < 8; i++) {
        int row = m0 + ty * 8 + i;
        if (row >= M) continue;
        float di = g_dinv[row];
        float dd = di * di;
        #pragma unroll
        for (int j = 0; j < 4; j++) {
            float2 v = unpack2(acc[i][j]);
            int col = tx * 8 + 2 * j;
            float c0 = fmaxf(v.x + bn[col],     0.f);
            float c1 = fmaxf(v.y + bn[col + 1], 0.f);
            g_xe [(size_t)row * S + col]     = c0;
            g_xe [(size_t)row * S + col + 1] = c1;
            g_pxe[(size_t)row * S + col]     = dd * c0;
            g_pxe[(size_t)row * S + col + 1] = dd * c1;
        }
    }
}

// ---------------- fused ZH GEMM + GRU activation + w0/w1 dot ------------------
__global__ __launch_bounds__(256)
void zhab_gemm_k(const float* __restrict__ Wout, int M) {
    __shared__ float As[8][128];
    __shared__ float Bs[2][8][128];
    __shared__ float red_a[128][17];
    __shared__ float red_b[128][17];
    int tid = threadIdx.x;
    int tx = tid & 15, ty = tid >> 4;
    int m0 = blockIdx.x * 128;
    int lrow = tid >> 1;
    int lkq  = (tid & 1) * 4;
    int bk = tid >> 5;
    int bn = (tid & 31) * 4;
    int arow = m0 + lrow;

    ull acc[2][8][4];
    #pragma unroll
    for (int h = 0; h < 2; h++)
        #pragma unroll
        for (int i = 0; i < 8; i++)
            #pragma unroll
            for (int j = 0; j < 4; j++) acc[h][i][j] = 0ull;

    for (int kk = 0; kk < S; kk += 8) {
        float4 av = make_float4(0.f, 0.f, 0.f, 0.f);
        if (arow < M) av = *(const float4*)(g_pxe + (size_t)arow * S + kk + lkq);
        As[lkq + 0][lrow] = av.x; As[lkq + 1][lrow] = av.y;
        As[lkq + 2][lrow] = av.z; As[lkq + 3][lrow] = av.w;
        #pragma unroll
        for (int h = 0; h < 2; h++) {
            float4 bv = *(const float4*)(g_Wcat + (size_t)(kk + bk) * 2 * S + h * S + bn);
            *(float4*)&Bs[h][bk][bn] = bv;
        }
        __syncthreads();
        #pragma unroll
        for (int k = 0; k < 8; k++) {
            float4 a0 = *(float4*)&As[k][ty * 8];
            float4 a1 = *(float4*)&As[k][ty * 8 + 4];
            ull aa[8] = {pack2(a0.x,a0.x), pack2(a0.y,a0.y), pack2(a0.z,a0.z), pack2(a0.w,a0.w),
                         pack2(a1.x,a1.x), pack2(a1.y,a1.y), pack2(a1.z,a1.z), pack2(a1.w,a1.w)};
            #pragma unroll
            for (int h = 0; h < 2; h++) {
                float4 b0 = *(float4*)&Bs[h][k][tx * 8];
                float4 b1 = *(float4*)&Bs[h][k][tx * 8 + 4];
                ull bb[4] = {pack2(b0.x,b0.y), pack2(b0.z,b0.w), pack2(b1.x,b1.y), pack2(b1.z,b1.w)};
                #pragma unroll
                for (int i = 0; i < 8; i++)
                    #pragma unroll
                    for (int j = 0; j < 4; j++)
                        ffma2(acc[h][i][j], aa[i], bb[j]);
            }
        }
        __syncthreads();
    }

    #pragma unroll
    for (int i = 0; i < 8; i++) {
        float pa = 0.f, pb = 0.f;
        #pragma unroll
        for (int j = 0; j < 4; j++) {
            float2 zv = unpack2(acc[0][i][j]);
            float2 hv = unpack2(acc[1][i][j]);
            int col = tx * 8 + 2 * j;
            #pragma unroll
            for (int q = 0; q < 2; q++) {
                float z = (q ? zv.y : zv.x) + g_bcat[col + q];
                float h = (q ? hv.y : hv.x) + g_bcat[S + col + q];
                float Z  = 1.f / (1.f + expf(-z));
                float Ht = tanhf(h);
                float Hv = (1.f - Z) * Ht;
                pa += Hv * Wout[col + q];
                pb += Hv * Wout[S + col + q];
            }
        }
        int row = ty * 8 + i;
        red_a[row][tx] = pa;
        red_b[row][tx] = pb;
    }
    __syncthreads();
    if (tid < 128) {
        float sa = 0.f, sb = 0.f;
        #pragma unroll
        for (int t = 0; t < 16; t++) { sa += red_a[tid][t]; sb += red_b[tid][t]; }
        int node = m0 + tid;
        if (node < M) { g_as[node] = sa; g_bs[node] = sb; }
    }
}

// ---------------- edge scatter (vector red) -----------------------------------
__global__ void scatter_k(int E) {
    int e = blockIdx.x * 8 + (threadIdx.x >> 5);
    if (e >= E) return;
    int lane = threadIdx.x & 31;
    int s = 0, d = 0; float c = 0.f;
    if (lane == 0) {
        s = g_src[e];
        d = g_dst[e];
        c = g_dinv[s] * g_dinv[d];
    }
    s = __shfl_sync(0xffffffffu, s, 0);
    d = __shfl_sync(0xffffffffu, d, 0);
    c = __shfl_sync(0xffffffffu, c, 0);
    float4 v = *((const float4*)(g_xe + (size_t)s * S) + lane);
    float* p = g_pxe + (size_t)d * S + lane * 4;
    asm volatile("red.global.add.v4.f32 [%0], {%1,%2,%3,%4};"
                 :: "l"(p), "f"(v.x * c), "f"(v.y * c), "f"(v.z * c), "f"(v.w * c)
                 : "memory");
}

// ---------------- fused edge GEMM + reduce (double-buffered) ------------------
// out[e] = relu(EA[e]@We + be) . w2  +  a[src] + b[dst] + bout
__global__ __launch_bounds__(256)
void edge_out_k(const float* __restrict__ EA, const float* __restrict__ We,
                const float* __restrict__ be, const float* __restrict__ Wout,
                const float* __restrict__ bout,
                float* __restrict__ out, int E) {
    __shared__ float As[2][8][128];
    __shared__ float Bs[2][8][128];
    __shared__ float red[128][17];
    int tid = threadIdx.x;
    int tx = tid & 15, ty = tid >> 4;
    int m0 = blockIdx.x * 128;
    int lrow = tid >> 1;
    int lkq  = (tid & 1) * 4;
    int bk = tid >> 5;
    int bn = (tid & 31) * 4;
    int arow = m0 + lrow;
    const int nsteps = 8;   // K = 64

    ull acc[8][4];
    #pragma unroll
    for (int i = 0; i < 8; i++)
        #pragma unroll
        for (int j = 0; j < 4; j++) acc[i][j] = 0ull;

    float4 av = make_float4(0.f, 0.f, 0.f, 0.f);
    if (arow < E) av = *(const float4*)(EA + (size_t)arow * 64 + lkq);
    float4 bv = *(const float4*)(We + (size_t)bk * 128 + bn);
    As[0][lkq + 0][lrow] = av.x; As[0][lkq + 1][lrow] = av.y;
    As[0][lkq + 2][lrow] = av.z; As[0][lkq + 3][lrow] = av.w;
    *(float4*)&Bs[0][bk][bn] = bv;
    __syncthreads();

    int cur = 0;
    for (int s = 0; s < nsteps; s++) {
        if (s + 1 < nsteps) {
            int kk = (s + 1) << 3;
            av = make_float4(0.f, 0.f, 0.f, 0.f);
            if (arow < E) av = *(const float4*)(EA + (size_t)arow * 64 + kk + lkq);
            bv = *(const float4*)(We + (size_t)(kk + bk) * 128 + bn);
        }
        #pragma unroll
        for (int k = 0; k < 8; k++) {
            float4 a0 = *(float4*)&As[cur][k][ty * 8];
            float4 a1 = *(float4*)&As[cur][k][ty * 8 + 4];
            float4 b0 = *(float4*)&Bs[cur][k][tx * 8];
            float4 b1 = *(float4*)&Bs[cur][k][tx * 8 + 4];
            ull aa[8] = {pack2(a0.x,a0.x), pack2(a0.y,a0.y), pack2(a0.z,a0.z), pack2(a0.w,a0.w),
                         pack2(a1.x,a1.x), pack2(a1.y,a1.y), pack2(a1.z,a1.z), pack2(a1.w,a1.w)};
            ull bb[4] = {pack2(b0.x,b0.y), pack2(b0.z,b0.w), pack2(b1.x,b1.y), pack2(b1.z,b1.w)};
            #pragma unroll
            for (int i = 0; i < 8; i++)
                #pragma unroll
                for (int j = 0; j < 4; j++)
                    ffma2(acc[i][j], aa[i], bb[j]);
        }
        if (s + 1 < nsteps) {
            int nxt = cur ^ 1;
            As[nxt][lkq + 0][lrow] = av.x; As[nxt][lkq + 1][lrow] = av.y;
            As[nxt][lkq + 2][lrow] = av.z; As[nxt][lkq + 3][lrow] = av.w;
            *(float4*)&Bs[nxt][bk][bn] = bv;
            __syncthreads();
            cur = nxt;
        }
    }
    const float* w2 = Wout + 2 * S;
    #pragma unroll
    for (int i = 0; i < 8; i++) {
        int row = ty * 8 + i;
        float p = 0.f;
        #pragma unroll
        for (int j = 0; j < 4; j++) {
            float2 v = unpack2(acc[i][j]);
            int col = tx * 8 + 2 * j;
            float c0 = fmaxf(v.x + be[col],     0.f);
            float c1 = fmaxf(v.y + be[col + 1], 0.f);
            p += c0 * w2[col] + c1 * w2[col + 1];
        }
        red[row][tx] = p;
    }
    __syncthreads();
    if (tid < 128) {
        float s = 0.f;
        #pragma unroll
        for (int t = 0; t < 16; t++) s += red[tid][t];
        int e = m0 + tid;
        if (e < E) {
            out[e] = s + g_as[g_src[e]] + g_bs[g_dst[e]] + bout[0];
        }
    }
}

// ---------------- launch: kernel launches ONLY --------------------------------
extern "C" void kernel_launch(void* const* d_in, const int* in_sizes, int n_in,
                              void* d_out, int out_size) {
    const float* x    = (const float*)d_in[0];
    const int*   ei32 = (const int*)d_in[1];   // int32 OR int64 (detected on-device)
    const float* ea   = (const float*)d_in[2];
    const float* Wn   = (const float*)d_in[3];
    const float* bn   = (const float*)d_in[4];
    const float* We   = (const float*)d_in[5];
    const float* be   = (const float*)d_in[6];
    const float* Wzc  = (const float*)d_in[7];
    const float* bzc  = (const float*)d_in[8];
    const float* Wzl  = (const float*)d_in[9];
    const float* bzl  = (const float*)d_in[10];
    // d_in[11..14] = Wrc, brc, Wrl, brl  -- dead (H=0 makes R unused)
    const float* Whc  = (const float*)d_in[15];
    const float* bhc  = (const float*)d_in[16];
    const float* Whl  = (const float*)d_in[17];
    const float* bhl  = (const float*)d_in[18];
    const float* Wout = (const float*)d_in[19];
    const float* bout = (const float*)d_in[20];
    float* out = (float*)d_out;

    int nN = in_sizes[0] / S;      // 50000
    int nE = in_sizes[2] / 64;     // 800000

    // 0) degree init, dtype detect, decode (+degree accumulate)
    deg_init_k<<<(nN + 255) / 256, 256>>>(nN);
    ei_detect_k<<<1, 256>>>(ei32, nE);
    ei_decode_k<<<(nE + 255) / 256, 256>>>(ei32, nE, nN);
    dinv_k<<<(nN + 255) / 256, 256>>>(nN);

    // 1) fold gate weights (tiny)
    prep_w_k<<<128, 256>>>(Wzc, Wzl, Whc, Whl);
    prep_b_k<<<256, 128>>>(bzc, Wzl, bzl, bhc, Whl, bhl);

    // 2) xe = relu(x@Wn+bn); pxe = dinv^2 * xe  (fused self-loop)
    xe_gemm_k<<<(nN + 127) / 128, 256>>>(x, Wn, bn, nN);

    // 3) scatter: pxe += norm * xe[src]  (vector red)
    scatter_k<<<(nE + 7) / 8, 256>>>(nE);

    // 4) fused: both gate GEMMs + GRU activation + w0/w1 dots -> g_as, g_bs
    zhab_gemm_k<<<(nN + 127) / 128, 256>>>(Wout, nN);

    // 5) fused edge GEMM + reduction + gather
    edge_out_k<<<(nE + 127) / 128, 256>>>(ea, We, be, Wout, bout, out, nE);
}

// round 16
// speedup vs baseline: 1.4448x; 1.0992x over previous
#include <cuda_runtime.h>
#include <math.h>

// Problem constants (fixed by the dataset)
#define NN 50000
#define NE 800000
#define S  128

typedef unsigned long long ull;

// ---------------- scratch (device globals; referenced directly) ---------------
__device__ float g_xe [(size_t)NN * S];      // relu(x@Wn+bn)
__device__ float g_pxe[(size_t)NN * S];      // normalized-adjacency propagated xe
__device__ float g_dinv[NN];
__device__ float g_as[NN];                   // H . w0
__device__ float g_bs[NN];                   // H . w1
__device__ float g_Wcat[S * 2 * S];          // [128][256] = [Wzc@Wzl_top | Whc@Whl_top]
__device__ float g_bcat[2 * S];
__device__ int   g_src[NE];                  // decoded edge sources
__device__ int   g_dst[NE];                  // decoded edge destinations
__device__ int   g_eimode;                   // 1 = int64 input layout, 0 = int32
// CSR build
__device__ int   g_cnt [NN];                 // in-degree histogram (no self loop)
__device__ int   g_scan[NN];                 // block-local inclusive scan
__device__ int   g_bsum[256];                // per-block sums (196 used)
__device__ int   g_off [NN + 1];             // CSR row offsets
__device__ int   g_cur [NN];                 // running fill cursor
__device__ int   g_csrc[NE];                 // edge sources grouped by dst
__device__ float g_cw  [NE];                 // per-edge norm coefficient

// ---------------- packed f32x2 helpers --------------------------------------
__device__ __forceinline__ ull pack2(float x, float y) {
    ull r; asm("mov.b64 %0, {%1,%2};" : "=l"(r) : "f"(x), "f"(y)); return r;
}
__device__ __forceinline__ void ffma2(ull &d, ull a, ull b) {
    asm("fma.rn.f32x2 %0, %1, %2, %0;" : "+l"(d) : "l"(a), "l"(b));
}
__device__ __forceinline__ float2 unpack2(ull v) {
    float2 f; asm("mov.b64 {%0,%1}, %2;" : "=f"(f.x), "=f"(f.y) : "l"(v)); return f;
}

// ---------------- edge-index dtype detection ----------------------------------
__global__ void ei_detect_k(const int* __restrict__ ei32, int E) {
    __shared__ int s_nonzero;
    if (threadIdx.x == 0) s_nonzero = 0;
    __syncthreads();
    int nsamp = 4096;
    if (nsamp > E) nsamp = E;
    int stride = (2 * E) / nsamp;
    if (stride < 1) stride = 1;
    int bad = 0;
    for (int k = threadIdx.x; k < nsamp; k += blockDim.x) {
        size_t entry = (size_t)k * stride;
        if (ei32[2 * entry + 1] != 0) bad = 1;
    }
    if (bad) atomicOr(&s_nonzero, 1);
    __syncthreads();
    if (threadIdx.x == 0) g_eimode = (s_nonzero == 0) ? 1 : 0;
}

__global__ void zero_cnt_k(int n) {
    int i = blockIdx.x * blockDim.x + threadIdx.x;
    if (i < n) g_cnt[i] = 0;
}

// decode + int in-degree histogram
__global__ void ei_decode_k(const int* __restrict__ ei32, int E, int n) {
    int e = blockIdx.x * blockDim.x + threadIdx.x;
    if (e >= E) return;
    int s, d;
    if (g_eimode) {
        s = ei32[2 * (size_t)e];
        d = ei32[2 * ((size_t)E + e)];
    } else {
        s = ei32[e];
        d = ei32[(size_t)E + e];
    }
    s = min(max(s, 0), n - 1);
    d = min(max(d, 0), n - 1);
    g_src[e] = s;
    g_dst[e] = d;
    atomicAdd(&g_cnt[d], 1);
}

// ---------------- xe GEMM (double-buffered, 2 blocks/SM) ----------------------
// g_xe = relu(x@Wn+bn).  (self-loop handled later in gather_k)
__global__ __launch_bounds__(256, 2)
void xe_gemm_k(const float* __restrict__ x, const float* __restrict__ Wn,
               const float* __restrict__ bn, int M) {
    __shared__ float As[2][8][128];
    __shared__ float Bs[2][8][128];
    int tid = threadIdx.x;
    int tx = tid & 15, ty = tid >> 4;
    int m0 = blockIdx.x * 128;
    int lrow = tid >> 1;
    int lkq  = (tid & 1) * 4;
    int bk = tid >> 5;
    int bn_ = (tid & 31) * 4;
    int arow = m0 + lrow;
    const int nsteps = S >> 3;   // 16

    ull acc[8][4];
    #pragma unroll
    for (int i = 0; i < 8; i++)
        #pragma unroll
        for (int j = 0; j < 4; j++) acc[i][j] = 0ull;

    float4 av = make_float4(0.f, 0.f, 0.f, 0.f);
    if (arow < M) av = *(const float4*)(x + (size_t)arow * S + lkq);
    float4 bv = *(const float4*)(Wn + (size_t)bk * S + bn_);
    As[0][lkq + 0][lrow] = av.x; As[0][lkq + 1][lrow] = av.y;
    As[0][lkq + 2][lrow] = av.z; As[0][lkq + 3][lrow] = av.w;
    *(float4*)&Bs[0][bk][bn_] = bv;
    __syncthreads();

    int cur = 0;
    for (int s = 0; s < nsteps; s++) {
        if (s + 1 < nsteps) {
            int kk = (s + 1) << 3;
            av = make_float4(0.f, 0.f, 0.f, 0.f);
            if (arow < M) av = *(const float4*)(x + (size_t)arow * S + kk + lkq);
            bv = *(const float4*)(Wn + (size_t)(kk + bk) * S + bn_);
        }
        #pragma unroll
        for (int k = 0; k < 8; k++) {
            float4 a0 = *(float4*)&As[cur][k][ty * 8];
            float4 a1 = *(float4*)&As[cur][k][ty * 8 + 4];
            float4 b0 = *(float4*)&Bs[cur][k][tx * 8];
            float4 b1 = *(float4*)&Bs[cur][k][tx * 8 + 4];
            ull aa[8] = {pack2(a0.x,a0.x), pack2(a0.y,a0.y), pack2(a0.z,a0.z), pack2(a0.w,a0.w),
                         pack2(a1.x,a1.x), pack2(a1.y,a1.y), pack2(a1.z,a1.z), pack2(a1.w,a1.w)};
            ull bb[4] = {pack2(b0.x,b0.y), pack2(b0.z,b0.w), pack2(b1.x,b1.y), pack2(b1.z,b1.w)};
            #pragma unroll
            for (int i = 0; i < 8; i++)
                #pragma unroll
                for (int j = 0; j < 4; j++)
                    ffma2(acc[i][j], aa[i], bb[j]);
        }
        if (s + 1 < nsteps) {
            int nxt = cur ^ 1;
            As[nxt][lkq + 0][lrow] = av.x; As[nxt][lkq + 1][lrow] = av.y;
            As[nxt][lkq + 2][lrow] = av.z; As[nxt][lkq + 3][lrow] = av.w;
            *(float4*)&Bs[nxt][bk][bn_] = bv;
            __syncthreads();
            cur = nxt;
        }
    }
    #pragma unroll
    for (int i = 0; i < 8; i++) {
        int row = m0 + ty * 8 + i;
        if (row >= M) continue;
        #pragma unroll
        for (int j = 0; j < 4; j++) {
            float2 v = unpack2(acc[i][j]);
            int col = tx * 8 + 2 * j;
            g_xe[(size_t)row * S + col]     = fmaxf(v.x + bn[col],     0.f);
            g_xe[(size_t)row * S + col + 1] = fmaxf(v.y + bn[col + 1], 0.f);
        }
    }
}

// ---------------- CSR build: scan + permute -----------------------------------
__global__ void scan1_k(int n) {
    __shared__ int sh[256];
    int i = blockIdx.x * 256 + threadIdx.x;
    int v = (i < n) ? g_cnt[i] : 0;
    sh[threadIdx.x] = v;
    __syncthreads();
    #pragma unroll
    for (int off = 1; off < 256; off <<= 1) {
        int t = (threadIdx.x >= off) ? sh[threadIdx.x - off] : 0;
        __syncthreads();
        sh[threadIdx.x] += t;
        __syncthreads();
    }
    if (i < n) g_scan[i] = sh[threadIdx.x];
    if (threadIdx.x == 255) g_bsum[blockIdx.x] = sh[255];
}

__global__ void scan2_k(int nb) {
    __shared__ int sh[256];
    int v = (threadIdx.x < nb) ? g_bsum[threadIdx.x] : 0;
    sh[threadIdx.x] = v;
    __syncthreads();
    #pragma unroll
    for (int off = 1; off < 256; off <<= 1) {
        int t = (threadIdx.x >= off) ? sh[threadIdx.x - off] : 0;
        __syncthreads();
        sh[threadIdx.x] += t;
        __syncthreads();
    }
    g_bsum[threadIdx.x] = sh[threadIdx.x];   // inclusive over block sums
}

__global__ void scan3_k(int n, int E) {
    int i = blockIdx.x * 256 + threadIdx.x;
    if (i >= n) return;
    int inc = g_scan[i] + (blockIdx.x > 0 ? g_bsum[blockIdx.x - 1] : 0);
    int cnt = g_cnt[i];
    int off = inc - cnt;                 // exclusive prefix
    g_off[i] = off;
    g_cur[i] = off;
    g_dinv[i] = rsqrtf(1.0f + (float)cnt);   // self-loop degree
    if (i == n - 1) g_off[n] = E;
}

__global__ void permute_k(int E) {
    int e = blockIdx.x * 256 + threadIdx.x;
    if (e >= E) return;
    int s = g_src[e], d = g_dst[e];
    int pos = atomicAdd(&g_cur[d], 1);
    g_csrc[pos] = s;
    g_cw[pos]   = g_dinv[s] * g_dinv[d];
}

// ---------------- CSR gather: pxe[d] = dinv^2*xe[d] + sum cw*xe[src] ---------
__global__ __launch_bounds__(256)
void gather_k(int n) {
    int node = blockIdx.x * 8 + (threadIdx.x >> 5);
    if (node >= n) return;
    int lane = threadIdx.x & 31;
    int e   = g_off[node];
    int end = g_off[node + 1];
    const float4* xe4 = (const float4*)g_xe;
    float4 acc = make_float4(0.f, 0.f, 0.f, 0.f);
    for (; e + 1 < end; e += 2) {
        int   s0 = g_csrc[e],   s1 = g_csrc[e + 1];
        float c0 = g_cw[e],     c1 = g_cw[e + 1];
        float4 v0 = xe4[(size_t)s0 * 32 + lane];
        float4 v1 = xe4[(size_t)s1 * 32 + lane];
        acc.x = fmaf(c0, v0.x, acc.x); acc.y = fmaf(c0, v0.y, acc.y);
        acc.z = fmaf(c0, v0.z, acc.z); acc.w = fmaf(c0, v0.w, acc.w);
        acc.x = fmaf(c1, v1.x, acc.x); acc.y = fmaf(c1, v1.y, acc.y);
        acc.z = fmaf(c1, v1.z, acc.z); acc.w = fmaf(c1, v1.w, acc.w);
    }
    if (e < end) {
        int   s0 = g_csrc[e];
        float c0 = g_cw[e];
        float4 v0 = xe4[(size_t)s0 * 32 + lane];
        acc.x = fmaf(c0, v0.x, acc.x); acc.y = fmaf(c0, v0.y, acc.y);
        acc.z = fmaf(c0, v0.z, acc.z); acc.w = fmaf(c0, v0.w, acc.w);
    }
    float di = g_dinv[node];
    float dd = di * di;
    float4 xv = xe4[(size_t)node * 32 + lane];
    acc.x = fmaf(dd, xv.x, acc.x); acc.y = fmaf(dd, xv.y, acc.y);
    acc.z = fmaf(dd, xv.z, acc.z); acc.w = fmaf(dd, xv.w, acc.w);
    ((float4*)g_pxe)[(size_t)node * 32 + lane] = acc;
}

// ---------------- weight folding --------------------------------------------
__global__ void prep_w_k(const float* __restrict__ Wzc, const float* __restrict__ Wzl,
                         const float* __restrict__ Whc, const float* __restrict__ Whl) {
    int k = blockIdx.x;
    int n = threadIdx.x;
    const float* Wc; const float* Wl; int nn;
    if (n < S) { Wc = Wzc + (size_t)k * S; Wl = Wzl; nn = n; }
    else       { Wc = Whc + (size_t)k * S; Wl = Whl; nn = n - S; }
    float s = 0.f;
    #pragma unroll 8
    for (int i = 0; i < S; i++) s += Wc[i] * Wl[(size_t)i * S + nn];
    g_Wcat[(size_t)k * 2 * S + n] = s;
}

__global__ void prep_b_k(const float* __restrict__ bzc, const float* __restrict__ Wzl,
                         const float* __restrict__ bzl,
                         const float* __restrict__ bhc, const float* __restrict__ Whl,
                         const float* __restrict__ bhl) {
    __shared__ float sred[4];
    int n = blockIdx.x;          // 0..255
    int t = threadIdx.x;         // 0..127
    const float* bc; const float* Wl; const float* bl; int nn;
    if (n < S) { bc = bzc; Wl = Wzl; bl = bzl; nn = n; }
    else       { bc = bhc; Wl = Whl; bl = bhl; nn = n - S; }
    float v = bc[t] * Wl[(size_t)t * S + nn];
    #pragma unroll
    for (int off = 16; off; off >>= 1) v += __shfl_down_sync(0xffffffffu, v, off);
    if ((t & 31) == 0) sred[t >> 5] = v;
    __syncthreads();
    if (t == 0) g_bcat[n] = sred[0] + sred[1] + sred[2] + sred[3] + bl[nn];
}

// ---------------- fused ZH GEMM + GRU activation + w0/w1 dot ------------------
__global__ __launch_bounds__(256)
void zhab_gemm_k(const float* __restrict__ Wout, int M) {
    __shared__ float As[8][128];
    __shared__ float Bs[2][8][128];
    __shared__ float red_a[128][17];
    __shared__ float red_b[128][17];
    int tid = threadIdx.x;
    int tx = tid & 15, ty = tid >> 4;
    int m0 = blockIdx.x * 128;
    int lrow = tid >> 1;
    int lkq  = (tid & 1) * 4;
    int bk = tid >> 5;
    int bn = (tid & 31) * 4;
    int arow = m0 + lrow;

    ull acc[2][8][4];
    #pragma unroll
    for (int h = 0; h < 2; h++)
        #pragma unroll
        for (int i = 0; i < 8; i++)
            #pragma unroll
            for (int j = 0; j < 4; j++) acc[h][i][j] = 0ull;

    for (int kk = 0; kk < S; kk += 8) {
        float4 av = make_float4(0.f, 0.f, 0.f, 0.f);
        if (arow < M) av = *(const float4*)(g_pxe + (size_t)arow * S + kk + lkq);
        As[lkq + 0][lrow] = av.x; As[lkq + 1][lrow] = av.y;
        As[lkq + 2][lrow] = av.z; As[lkq + 3][lrow] = av.w;
        #pragma unroll
        for (int h = 0; h < 2; h++) {
            float4 bv = *(const float4*)(g_Wcat + (size_t)(kk + bk) * 2 * S + h * S + bn);
            *(float4*)&Bs[h][bk][bn] = bv;
        }
        __syncthreads();
        #pragma unroll
        for (int k = 0; k < 8; k++) {
            float4 a0 = *(float4*)&As[k][ty * 8];
            float4 a1 = *(float4*)&As[k][ty * 8 + 4];
            ull aa[8] = {pack2(a0.x,a0.x), pack2(a0.y,a0.y), pack2(a0.z,a0.z), pack2(a0.w,a0.w),
                         pack2(a1.x,a1.x), pack2(a1.y,a1.y), pack2(a1.z,a1.z), pack2(a1.w,a1.w)};
            #pragma unroll
            for (int h = 0; h < 2; h++) {
                float4 b0 = *(float4*)&Bs[h][k][tx * 8];
                float4 b1 = *(float4*)&Bs[h][k][tx * 8 + 4];
                ull bb[4] = {pack2(b0.x,b0.y), pack2(b0.z,b0.w), pack2(b1.x,b1.y), pack2(b1.z,b1.w)};
                #pragma unroll
                for (int i = 0; i < 8; i++)
                    #pragma unroll
                    for (int j = 0; j < 4; j++)
                        ffma2(acc[h][i][j], aa[i], bb[j]);
            }
        }
        __syncthreads();
    }

    #pragma unroll
    for (int i = 0; i < 8; i++) {
        float pa = 0.f, pb = 0.f;
        #pragma unroll
        for (int j = 0; j < 4; j++) {
            float2 zv = unpack2(acc[0][i][j]);
            float2 hv = unpack2(acc[1][i][j]);
            int col = tx * 8 + 2 * j;
            #pragma unroll
            for (int q = 0; q < 2; q++) {
                float z = (q ? zv.y : zv.x) + g_bcat[col + q];
                float h = (q ? hv.y : hv.x) + g_bcat[S + col + q];
                float Z  = 1.f / (1.f + expf(-z));
                float Ht = tanhf(h);
                float Hv = (1.f - Z) * Ht;
                pa += Hv * Wout[col + q];
                pb += Hv * Wout[S + col + q];
            }
        }
        int row = ty * 8 + i;
        red_a[row][tx] = pa;
        red_b[row][tx] = pb;
    }
    __syncthreads();
    if (tid < 128) {
        float sa = 0.f, sb = 0.f;
        #pragma unroll
        for (int t = 0; t < 16; t++) { sa += red_a[tid][t]; sb += red_b[tid][t]; }
        int node = m0 + tid;
        if (node < M) { g_as[node] = sa; g_bs[node] = sb; }
    }
}

// ---------------- fused edge GEMM + reduce (double-buffered, 2 blocks/SM) -----
// out[e] = relu(EA[e]@We + be) . w2  +  a[src] + b[dst] + bout
__global__ __launch_bounds__(256, 2)
void edge_out_k(const float* __restrict__ EA, const float* __restrict__ We,
                const float* __restrict__ be, const float* __restrict__ Wout,
                const float* __restrict__ bout,
                float* __restrict__ out, int E) {
    __shared__ float As[2][8][128];
    __shared__ float Bs[2][8][128];
    __shared__ float red[128][17];
    int tid = threadIdx.x;
    int tx = tid & 15, ty = tid >> 4;
    int m0 = blockIdx.x * 128;
    int lrow = tid >> 1;
    int lkq  = (tid & 1) * 4;
    int bk = tid >> 5;
    int bn = (tid & 31) * 4;
    int arow = m0 + lrow;
    const int nsteps = 8;   // K = 64

    ull acc[8][4];
    #pragma unroll
    for (int i = 0; i < 8; i++)
        #pragma unroll
        for (int j = 0; j < 4; j++) acc[i][j] = 0ull;

    float4 av = make_float4(0.f, 0.f, 0.f, 0.f);
    if (arow < E) av = *(const float4*)(EA + (size_t)arow * 64 + lkq);
    float4 bv = *(const float4*)(We + (size_t)bk * 128 + bn);
    As[0][lkq + 0][lrow] = av.x; As[0][lkq + 1][lrow] = av.y;
    As[0][lkq + 2][lrow] = av.z; As[0][lkq + 3][lrow] = av.w;
    *(float4*)&Bs[0][bk][bn] = bv;
    __syncthreads();

    int cur = 0;
    for (int s = 0; s < nsteps; s++) {
        if (s + 1 < nsteps) {
            int kk = (s + 1) << 3;
            av = make_float4(0.f, 0.f, 0.f, 0.f);
            if (arow < E) av = *(const float4*)(EA + (size_t)arow * 64 + kk + lkq);
            bv = *(const float4*)(We + (size_t)(kk + bk) * 128 + bn);
        }
        #pragma unroll
        for (int k = 0; k < 8; k++) {
            float4 a0 = *(float4*)&As[cur][k][ty * 8];
            float4 a1 = *(float4*)&As[cur][k][ty * 8 + 4];
            float4 b0 = *(float4*)&Bs[cur][k][tx * 8];
            float4 b1 = *(float4*)&Bs[cur][k][tx * 8 + 4];
            ull aa[8] = {pack2(a0.x,a0.x), pack2(a0.y,a0.y), pack2(a0.z,a0.z), pack2(a0.w,a0.w),
                         pack2(a1.x,a1.x), pack2(a1.y,a1.y), pack2(a1.z,a1.z), pack2(a1.w,a1.w)};
            ull bb[4] = {pack2(b0.x,b0.y), pack2(b0.z,b0.w), pack2(b1.x,b1.y), pack2(b1.z,b1.w)};
            #pragma unroll
            for (int i = 0; i < 8; i++)
                #pragma unroll
                for (int j = 0; j < 4; j++)
                    ffma2(acc[i][j], aa[i], bb[j]);
        }
        if (s + 1 < nsteps) {
            int nxt = cur ^ 1;
            As[nxt][lkq + 0][lrow] = av.x; As[nxt][lkq + 1][lrow] = av.y;
            As[nxt][lkq + 2][lrow] = av.z; As[nxt][lkq + 3][lrow] = av.w;
            *(float4*)&Bs[nxt][bk][bn] = bv;
            __syncthreads();
            cur = nxt;
        }
    }
    const float* w2 = Wout + 2 * S;
    #pragma unroll
    for (int i = 0; i < 8; i++) {
        int row = ty * 8 + i;
        float p = 0.f;
        #pragma unroll
        for (int j = 0; j < 4; j++) {
            float2 v = unpack2(acc[i][j]);
            int col = tx * 8 + 2 * j;
            float c0 = fmaxf(v.x + be[col],     0.f);
            float c1 = fmaxf(v.y + be[col + 1], 0.f);
            p += c0 * w2[col] + c1 * w2[col + 1];
        }
        red[row][tx] = p;
    }
    __syncthreads();
    if (tid < 128) {
        float s = 0.f;
        #pragma unroll
        for (int t = 0; t < 16; t++) s += red[tid][t];
        int e = m0 + tid;
        if (e < E) {
            out[e] = s + g_as[g_src[e]] + g_bs[g_dst[e]] + bout[0];
        }
    }
}

// ---------------- launch: kernel launches ONLY --------------------------------
extern "C" void kernel_launch(void* const* d_in, const int* in_sizes, int n_in,
                              void* d_out, int out_size) {
    const float* x    = (const float*)d_in[0];
    const int*   ei32 = (const int*)d_in[1];   // int32 OR int64 (detected on-device)
    const float* ea   = (const float*)d_in[2];
    const float* Wn   = (const float*)d_in[3];
    const float* bn   = (const float*)d_in[4];
    const float* We   = (const float*)d_in[5];
    const float* be   = (const float*)d_in[6];
    const float* Wzc  = (const float*)d_in[7];
    const float* bzc  = (const float*)d_in[8];
    const float* Wzl  = (const float*)d_in[9];
    const float* bzl  = (const float*)d_in[10];
    // d_in[11..14] = Wrc, brc, Wrl, brl  -- dead (H=0 makes R unused)
    const float* Whc  = (const float*)d_in[15];
    const float* bhc  = (const float*)d_in[16];
    const float* Whl  = (const float*)d_in[17];
    const float* bhl  = (const float*)d_in[18];
    const float* Wout = (const float*)d_in[19];
    const float* bout = (const float*)d_in[20];
    float* out = (float*)d_out;

    int nN = in_sizes[0] / S;      // 50000
    int nE = in_sizes[2] / 64;     // 800000
    int nScanBlocks = (nN + 255) / 256;   // 196

    // 0-2) dtype detect, zero histogram, decode (+in-degree count)
    ei_detect_k<<<1, 256>>>(ei32, nE);
    zero_cnt_k<<<(nN + 255) / 256, 256>>>(nN);
    ei_decode_k<<<(nE + 255) / 256, 256>>>(ei32, nE, nN);

    // 3) xe = relu(x@Wn+bn)   <-- launch index 3: gets the ncu profile window
    xe_gemm_k<<<(nN + 127) / 128, 256>>>(x, Wn, bn, nN);

    // 4-6) CSR offsets: block scan, scan of block sums, combine (+dinv)
    scan1_k<<<nScanBlocks, 256>>>(nN);
    scan2_k<<<1, 256>>>(nScanBlocks);
    scan3_k<<<nScanBlocks, 256>>>(nN, nE);

    // 7-8) fold gate weights (independent, tiny)
    prep_w_k<<<128, 256>>>(Wzc, Wzl, Whc, Whl);
    prep_b_k<<<256, 128>>>(bzc, Wzl, bzl, bhc, Whl, bhl);

    // 9) group edges by destination (CSR fill)
    permute_k<<<(nE + 255) / 256, 256>>>(nE);

    // 10) gather: pxe = dinv^2*xe + sum cw*xe[src]   (no atomics)
    gather_k<<<(nN + 7) / 8, 256>>>(nN);

    // 11) fused: both gate GEMMs + GRU activation + w0/w1 dots -> g_as, g_bs
    zhab_gemm_k<<<(nN + 127) / 128, 256>>>(Wout, nN);

    // 12) fused edge GEMM + reduction + gather
    edge_out_k<<<(nE + 127) / 128, 256>>>(ea, We, be, Wout, bout, out, nE);
}

// round 17
// speedup vs baseline: 2.0986x; 1.4526x over previous
#include <cuda_runtime.h>
#include <math.h>

// Problem constants (fixed by the dataset)
#define NN 50000
#define NE 800000
#define S  128

typedef unsigned long long ull;

// ---------------- scratch (device globals; referenced directly) ---------------
__device__ float g_xe [(size_t)NN * S];      // relu(x@Wn+bn)
__device__ float g_pxe[(size_t)NN * S];      // normalized-adjacency propagated xe
__device__ float g_dinv[NN];
__device__ float g_as[NN];                   // H . w0
__device__ float g_bs[NN];                   // H . w1
__device__ float g_Wcat[S * 2 * S];          // [128][256] = [Wzc@Wzl_top | Whc@Whl_top]
__device__ float g_bcat[2 * S];
__device__ int   g_src[NE];                  // decoded edge sources
__device__ int   g_dst[NE];                  // decoded edge destinations
__device__ int   g_eimode;                   // 1 = int64 input layout, 0 = int32
// CSR build
__device__ int   g_cnt [NN];                 // in-degree histogram (no self loop)
__device__ int   g_scan[NN];                 // block-local inclusive scan
__device__ int   g_bsum[256];                // per-block sums (196 used)
__device__ int   g_off [NN + 1];             // CSR row offsets
__device__ int   g_cur [NN];                 // running fill cursor
__device__ int   g_csrc[NE];                 // edge sources grouped by dst
__device__ float g_cw  [NE];                 // per-edge norm coefficient

// ---------------- packed f32x2 helpers --------------------------------------
__device__ __forceinline__ ull pack2(float x, float y) {
    ull r; asm("mov.b64 %0, {%1,%2};" : "=l"(r) : "f"(x), "f"(y)); return r;
}
__device__ __forceinline__ void ffma2(ull &d, ull a, ull b) {
    asm("fma.rn.f32x2 %0, %1, %2, %0;" : "+l"(d) : "l"(a), "l"(b));
}
__device__ __forceinline__ float2 unpack2(ull v) {
    float2 f; asm("mov.b64 {%0,%1}, %2;" : "=f"(f.x), "=f"(f.y) : "l"(v)); return f;
}

// ---------------- tf32 helpers -----------------------------------------------
__device__ __forceinline__ unsigned int f2tf32(float f) {
    unsigned int u; asm("cvt.rna.tf32.f32 %0, %1;" : "=r"(u) : "f"(f)); return u;
}
__device__ __forceinline__ void mma_tf32(float* c,
        unsigned int a0, unsigned int a1, unsigned int a2, unsigned int a3,
        unsigned int b0, unsigned int b1) {
    asm volatile("mma.sync.aligned.m16n8k8.row.col.f32.tf32.tf32.f32 "
        "{%0,%1,%2,%3}, {%4,%5,%6,%7}, {%8,%9}, {%0,%1,%2,%3};"
        : "+f"(c[0]), "+f"(c[1]), "+f"(c[2]), "+f"(c[3])
        : "r"(a0), "r"(a1), "r"(a2), "r"(a3), "r"(b0), "r"(b1));
}

// ---------------- edge-index dtype detection ----------------------------------
__global__ void ei_detect_k(const int* __restrict__ ei32, int E) {
    __shared__ int s_nonzero;
    if (threadIdx.x == 0) s_nonzero = 0;
    __syncthreads();
    int nsamp = 4096;
    if (nsamp > E) nsamp = E;
    int stride = (2 * E) / nsamp;
    if (stride < 1) stride = 1;
    int bad = 0;
    for (int k = threadIdx.x; k < nsamp; k += blockDim.x) {
        size_t entry = (size_t)k * stride;
        if (ei32[2 * entry + 1] != 0) bad = 1;
    }
    if (bad) atomicOr(&s_nonzero, 1);
    __syncthreads();
    if (threadIdx.x == 0) g_eimode = (s_nonzero == 0) ? 1 : 0;
}

__global__ void zero_cnt_k(int n) {
    int i = blockIdx.x * blockDim.x + threadIdx.x;
    if (i < n) g_cnt[i] = 0;
}

// decode + int in-degree histogram
__global__ void ei_decode_k(const int* __restrict__ ei32, int E, int n) {
    int e = blockIdx.x * blockDim.x + threadIdx.x;
    if (e >= E) return;
    int s, d;
    if (g_eimode) {
        s = ei32[2 * (size_t)e];
        d = ei32[2 * ((size_t)E + e)];
    } else {
        s = ei32[e];
        d = ei32[(size_t)E + e];
    }
    s = min(max(s, 0), n - 1);
    d = min(max(d, 0), n - 1);
    g_src[e] = s;
    g_dst[e] = d;
    atomicAdd(&g_cnt[d], 1);
}

// ---------------- xe GEMM (double-buffered, 2 blocks/SM) ----------------------
__global__ __launch_bounds__(256, 2)
void xe_gemm_k(const float* __restrict__ x, const float* __restrict__ Wn,
               const float* __restrict__ bn, int M) {
    __shared__ float As[2][8][128];
    __shared__ float Bs[2][8][128];
    int tid = threadIdx.x;
    int tx = tid & 15, ty = tid >> 4;
    int m0 = blockIdx.x * 128;
    int lrow = tid >> 1;
    int lkq  = (tid & 1) * 4;
    int bk = tid >> 5;
    int bn_ = (tid & 31) * 4;
    int arow = m0 + lrow;
    const int nsteps = S >> 3;   // 16

    ull acc[8][4];
    #pragma unroll
    for (int i = 0; i < 8; i++)
        #pragma unroll
        for (int j = 0; j < 4; j++) acc[i][j] = 0ull;

    float4 av = make_float4(0.f, 0.f, 0.f, 0.f);
    if (arow < M) av = *(const float4*)(x + (size_t)arow * S + lkq);
    float4 bv = *(const float4*)(Wn + (size_t)bk * S + bn_);
    As[0][lkq + 0][lrow] = av.x; As[0][lkq + 1][lrow] = av.y;
    As[0][lkq + 2][lrow] = av.z; As[0][lkq + 3][lrow] = av.w;
    *(float4*)&Bs[0][bk][bn_] = bv;
    __syncthreads();

    int cur = 0;
    for (int s = 0; s < nsteps; s++) {
        if (s + 1 < nsteps) {
            int kk = (s + 1) << 3;
            av = make_float4(0.f, 0.f, 0.f, 0.f);
            if (arow < M) av = *(const float4*)(x + (size_t)arow * S + kk + lkq);
            bv = *(const float4*)(Wn + (size_t)(kk + bk) * S + bn_);
        }
        #pragma unroll
        for (int k = 0; k < 8; k++) {
            float4 a0 = *(float4*)&As[cur][k][ty * 8];
            float4 a1 = *(float4*)&As[cur][k][ty * 8 + 4];
            float4 b0 = *(float4*)&Bs[cur][k][tx * 8];
            float4 b1 = *(float4*)&Bs[cur][k][tx * 8 + 4];
            ull aa[8] = {pack2(a0.x,a0.x), pack2(a0.y,a0.y), pack2(a0.z,a0.z), pack2(a0.w,a0.w),
                         pack2(a1.x,a1.x), pack2(a1.y,a1.y), pack2(a1.z,a1.z), pack2(a1.w,a1.w)};
            ull bb[4] = {pack2(b0.x,b0.y), pack2(b0.z,b0.w), pack2(b1.x,b1.y), pack2(b1.z,b1.w)};
            #pragma unroll
            for (int i = 0; i < 8; i++)
                #pragma unroll
                for (int j = 0; j < 4; j++)
                    ffma2(acc[i][j], aa[i], bb[j]);
        }
        if (s + 1 < nsteps) {
            int nxt = cur ^ 1;
            As[nxt][lkq + 0][lrow] = av.x; As[nxt][lkq + 1][lrow] = av.y;
            As[nxt][lkq + 2][lrow] = av.z; As[nxt][lkq + 3][lrow] = av.w;
            *(float4*)&Bs[nxt][bk][bn_] = bv;
            __syncthreads();
            cur = nxt;
        }
    }
    #pragma unroll
    for (int i = 0; i < 8; i++) {
        int row = m0 + ty * 8 + i;
        if (row >= M) continue;
        #pragma unroll
        for (int j = 0; j < 4; j++) {
            float2 v = unpack2(acc[i][j]);
            int col = tx * 8 + 2 * j;
            g_xe[(size_t)row * S + col]     = fmaxf(v.x + bn[col],     0.f);
            g_xe[(size_t)row * S + col + 1] = fmaxf(v.y + bn[col + 1], 0.f);
        }
    }
}

// ---------------- CSR build: scan + permute -----------------------------------
__global__ void scan1_k(int n) {
    __shared__ int sh[256];
    int i = blockIdx.x * 256 + threadIdx.x;
    int v = (i < n) ? g_cnt[i] : 0;
    sh[threadIdx.x] = v;
    __syncthreads();
    #pragma unroll
    for (int off = 1; off < 256; off <<= 1) {
        int t = (threadIdx.x >= off) ? sh[threadIdx.x - off] : 0;
        __syncthreads();
        sh[threadIdx.x] += t;
        __syncthreads();
    }
    if (i < n) g_scan[i] = sh[threadIdx.x];
    if (threadIdx.x == 255) g_bsum[blockIdx.x] = sh[255];
}

__global__ void scan2_k(int nb) {
    __shared__ int sh[256];
    int v = (threadIdx.x < nb) ? g_bsum[threadIdx.x] : 0;
    sh[threadIdx.x] = v;
    __syncthreads();
    #pragma unroll
    for (int off = 1; off < 256; off <<= 1) {
        int t = (threadIdx.x >= off) ? sh[threadIdx.x - off] : 0;
        __syncthreads();
        sh[threadIdx.x] += t;
        __syncthreads();
    }
    g_bsum[threadIdx.x] = sh[threadIdx.x];   // inclusive over block sums
}

__global__ void scan3_k(int n, int E) {
    int i = blockIdx.x * 256 + threadIdx.x;
    if (i >= n) return;
    int inc = g_scan[i] + (blockIdx.x > 0 ? g_bsum[blockIdx.x - 1] : 0);
    int cnt = g_cnt[i];
    int off = inc - cnt;                 // exclusive prefix
    g_off[i] = off;
    g_cur[i] = off;
    g_dinv[i] = rsqrtf(1.0f + (float)cnt);   // self-loop degree
    if (i == n - 1) g_off[n] = E;
}

__global__ void permute_k(int E) {
    int e = blockIdx.x * 256 + threadIdx.x;
    if (e >= E) return;
    int s = g_src[e], d = g_dst[e];
    int pos = atomicAdd(&g_cur[d], 1);
    g_csrc[pos] = s;
    g_cw[pos]   = g_dinv[s] * g_dinv[d];
}

// ---------------- CSR gather: pxe[d] = dinv^2*xe[d] + sum cw*xe[src] ---------
__global__ __launch_bounds__(256)
void gather_k(int n) {
    int node = blockIdx.x * 8 + (threadIdx.x >> 5);
    if (node >= n) return;
    int lane = threadIdx.x & 31;
    int e   = g_off[node];
    int end = g_off[node + 1];
    const float4* xe4 = (const float4*)g_xe;
    float4 acc = make_float4(0.f, 0.f, 0.f, 0.f);
    for (; e + 1 < end; e += 2) {
        int   s0 = g_csrc[e],   s1 = g_csrc[e + 1];
        float c0 = g_cw[e],     c1 = g_cw[e + 1];
        float4 v0 = xe4[(size_t)s0 * 32 + lane];
        float4 v1 = xe4[(size_t)s1 * 32 + lane];
        acc.x = fmaf(c0, v0.x, acc.x); acc.y = fmaf(c0, v0.y, acc.y);
        acc.z = fmaf(c0, v0.z, acc.z); acc.w = fmaf(c0, v0.w, acc.w);
        acc.x = fmaf(c1, v1.x, acc.x); acc.y = fmaf(c1, v1.y, acc.y);
        acc.z = fmaf(c1, v1.z, acc.z); acc.w = fmaf(c1, v1.w, acc.w);
    }
    if (e < end) {
        int   s0 = g_csrc[e];
        float c0 = g_cw[e];
        float4 v0 = xe4[(size_t)s0 * 32 + lane];
        acc.x = fmaf(c0, v0.x, acc.x); acc.y = fmaf(c0, v0.y, acc.y);
        acc.z = fmaf(c0, v0.z, acc.z); acc.w = fmaf(c0, v0.w, acc.w);
    }
    float di = g_dinv[node];
    float dd = di * di;
    float4 xv = xe4[(size_t)node * 32 + lane];
    acc.x = fmaf(dd, xv.x, acc.x); acc.y = fmaf(dd, xv.y, acc.y);
    acc.z = fmaf(dd, xv.z, acc.z); acc.w = fmaf(dd, xv.w, acc.w);
    ((float4*)g_pxe)[(size_t)node * 32 + lane] = acc;
}

// ---------------- weight folding --------------------------------------------
__global__ void prep_w_k(const float* __restrict__ Wzc, const float* __restrict__ Wzl,
                         const float* __restrict__ Whc, const float* __restrict__ Whl) {
    int k = blockIdx.x;
    int n = threadIdx.x;
    const float* Wc; const float* Wl; int nn;
    if (n < S) { Wc = Wzc + (size_t)k * S; Wl = Wzl; nn = n; }
    else       { Wc = Whc + (size_t)k * S; Wl = Whl; nn = n - S; }
    float s = 0.f;
    #pragma unroll 8
    for (int i = 0; i < S; i++) s += Wc[i] * Wl[(size_t)i * S + nn];
    g_Wcat[(size_t)k * 2 * S + n] = s;
}

__global__ void prep_b_k(const float* __restrict__ bzc, const float* __restrict__ Wzl,
                         const float* __restrict__ bzl,
                         const float* __restrict__ bhc, const float* __restrict__ Whl,
                         const float* __restrict__ bhl) {
    __shared__ float sred[4];
    int n = blockIdx.x;          // 0..255
    int t = threadIdx.x;         // 0..127
    const float* bc; const float* Wl; const float* bl; int nn;
    if (n < S) { bc = bzc; Wl = Wzl; bl = bzl; nn = n; }
    else       { bc = bhc; Wl = Whl; bl = bhl; nn = n - S; }
    float v = bc[t] * Wl[(size_t)t * S + nn];
    #pragma unroll
    for (int off = 16; off; off >>= 1) v += __shfl_down_sync(0xffffffffu, v, off);
    if ((t & 31) == 0) sred[t >> 5] = v;
    __syncthreads();
    if (t == 0) g_bcat[n] = sred[0] + sred[1] + sred[2] + sred[3] + bl[nn];
}

// ---------------- fused ZH GEMM + GRU activation + w0/w1 dot ------------------
__global__ __launch_bounds__(256)
void zhab_gemm_k(const float* __restrict__ Wout, int M) {
    __shared__ float As[8][128];
    __shared__ float Bs[2][8][128];
    __shared__ float red_a[128][17];
    __shared__ float red_b[128][17];
    int tid = threadIdx.x;
    int tx = tid & 15, ty = tid >> 4;
    int m0 = blockIdx.x * 128;
    int lrow = tid >> 1;
    int lkq  = (tid & 1) * 4;
    int bk = tid >> 5;
    int bn = (tid & 31) * 4;
    int arow = m0 + lrow;

    ull acc[2][8][4];
    #pragma unroll
    for (int h = 0; h < 2; h++)
        #pragma unroll
        for (int i = 0; i < 8; i++)
            #pragma unroll
            for (int j = 0; j < 4; j++) acc[h][i][j] = 0ull;

    for (int kk = 0; kk < S; kk += 8) {
        float4 av = make_float4(0.f, 0.f, 0.f, 0.f);
        if (arow < M) av = *(const float4*)(g_pxe + (size_t)arow * S + kk + lkq);
        As[lkq + 0][lrow] = av.x; As[lkq + 1][lrow] = av.y;
        As[lkq + 2][lrow] = av.z; As[lkq + 3][lrow] = av.w;
        #pragma unroll
        for (int h = 0; h < 2; h++) {
            float4 bv = *(const float4*)(g_Wcat + (size_t)(kk + bk) * 2 * S + h * S + bn);
            *(float4*)&Bs[h][bk][bn] = bv;
        }
        __syncthreads();
        #pragma unroll
        for (int k = 0; k < 8; k++) {
            float4 a0 = *(float4*)&As[k][ty * 8];
            float4 a1 = *(float4*)&As[k][ty * 8 + 4];
            ull aa[8] = {pack2(a0.x,a0.x), pack2(a0.y,a0.y), pack2(a0.z,a0.z), pack2(a0.w,a0.w),
                         pack2(a1.x,a1.x), pack2(a1.y,a1.y), pack2(a1.z,a1.z), pack2(a1.w,a1.w)};
            #pragma unroll
            for (int h = 0; h < 2; h++) {
                float4 b0 = *(float4*)&Bs[h][k][tx * 8];
                float4 b1 = *(float4*)&Bs[h][k][tx * 8 + 4];
                ull bb[4] = {pack2(b0.x,b0.y), pack2(b0.z,b0.w), pack2(b1.x,b1.y), pack2(b1.z,b1.w)};
                #pragma unroll
                for (int i = 0; i < 8; i++)
                    #pragma unroll
                    for (int j = 0; j < 4; j++)
                        ffma2(acc[h][i][j], aa[i], bb[j]);
            }
        }
        __syncthreads();
    }

    #pragma unroll
    for (int i = 0; i < 8; i++) {
        float pa = 0.f, pb = 0.f;
        #pragma unroll
        for (int j = 0; j < 4; j++) {
            float2 zv = unpack2(acc[0][i][j]);
            float2 hv = unpack2(acc[1][i][j]);
            int col = tx * 8 + 2 * j;
            #pragma unroll
            for (int q = 0; q < 2; q++) {
                float z = (q ? zv.y : zv.x) + g_bcat[col + q];
                float h = (q ? hv.y : hv.x) + g_bcat[S + col + q];
                float Z  = 1.f / (1.f + expf(-z));
                float Ht = tanhf(h);
                float Hv = (1.f - Z) * Ht;
                pa += Hv * Wout[col + q];
                pb += Hv * Wout[S + col + q];
            }
        }
        int row = ty * 8 + i;
        red_a[row][tx] = pa;
        red_b[row][tx] = pb;
    }
    __syncthreads();
    if (tid < 128) {
        float sa = 0.f, sb = 0.f;
        #pragma unroll
        for (int t = 0; t < 16; t++) { sa += red_a[tid][t]; sb += red_b[tid][t]; }
        int node = m0 + tid;
        if (node < M) { g_as[node] = sa; g_bs[node] = sb; }
    }
}

// ---------------- fused edge GEMM via tf32 tensor MMA -------------------------
// out[e] = relu(EA[e]@We + be) . w2  +  a[src] + b[dst] + bout
// Tile: 128 edges x 128 cols, K=64 in two 32-wide phases.
// 8 warps in 4m x 2n grid; warp tile 32x64 (2 m-tiles x 8 n-tiles of m16n8k8).
__global__ __launch_bounds__(256, 2)
void edge_out_k(const float* __restrict__ EA, const float* __restrict__ We,
                const float* __restrict__ be, const float* __restrict__ Wout,
                const float* __restrict__ bout,
                float* __restrict__ out, int E) {
    __shared__ unsigned int As[128][36];   // tf32 bits, [row][k-in-phase], pad->conflict-free
    __shared__ unsigned int Bs[32][136];   // tf32 bits, [k-in-phase][col]
    __shared__ float sbe[128], sw2[128];
    __shared__ float red[128][2];
    int tid = threadIdx.x;
    int m0 = blockIdx.x * 128;
    int lane = tid & 31, w = tid >> 5;
    int wm = w >> 1, wn = w & 1;          // 4 x 2 warp grid
    int r4 = lane >> 2, c4 = lane & 3;

    if (tid < 128) { sbe[tid] = be[tid]; sw2[tid] = Wout[2 * S + tid]; }

    float acc[2][8][4];
    #pragma unroll
    for (int mt = 0; mt < 2; mt++)
        #pragma unroll
        for (int j = 0; j < 8; j++)
            #pragma unroll
            for (int q = 0; q < 4; q++) acc[mt][j][q] = 0.f;

    #pragma unroll
    for (int p = 0; p < 2; p++) {
        int kbase = p * 32;
        // load A tile: 128 rows x 32 cols (2 threads/row, 16 floats each)
        {
            int row  = tid >> 1;
            int col0 = (tid & 1) * 16;
            int arow = m0 + row;
            float v[16];
            if (arow < E) {
                const float4* src = (const float4*)(EA + (size_t)arow * 64 + kbase + col0);
                #pragma unroll
                for (int i = 0; i < 4; i++) {
                    float4 f = src[i];
                    v[4*i] = f.x; v[4*i+1] = f.y; v[4*i+2] = f.z; v[4*i+3] = f.w;
                }
            } else {
                #pragma unroll
                for (int i = 0; i < 16; i++) v[i] = 0.f;
            }
            #pragma unroll
            for (int i = 0; i < 16; i++) As[row][col0 + i] = f2tf32(v[i]);
        }
        // load B tile: 32 rows x 128 cols (8 threads/row, 16 floats each)
        {
            int row  = tid >> 3;
            int col0 = (tid & 7) * 16;
            const float4* src = (const float4*)(We + (size_t)(kbase + row) * 128 + col0);
            #pragma unroll
            for (int i = 0; i < 4; i++) {
                float4 f = src[i];
                Bs[row][col0 + 4*i]     = f2tf32(f.x);
                Bs[row][col0 + 4*i + 1] = f2tf32(f.y);
                Bs[row][col0 + 4*i + 2] = f2tf32(f.z);
                Bs[row][col0 + 4*i + 3] = f2tf32(f.w);
            }
        }
        __syncthreads();
        #pragma unroll
        for (int k = 0; k < 4; k++) {
            int k0 = k * 8;
            unsigned int bfr[8][2];
            #pragma unroll
            for (int j = 0; j < 8; j++) {
                int col = wn * 64 + j * 8 + r4;
                bfr[j][0] = Bs[k0 + c4][col];
                bfr[j][1] = Bs[k0 + 4 + c4][col];
            }
            #pragma unroll
            for (int mt = 0; mt < 2; mt++) {
                int row = wm * 32 + mt * 16 + r4;
                unsigned int a0 = As[row][k0 + c4];
                unsigned int a1 = As[row + 8][k0 + c4];
                unsigned int a2 = As[row][k0 + c4 + 4];
                unsigned int a3 = As[row + 8][k0 + c4 + 4];
                #pragma unroll
                for (int j = 0; j < 8; j++)
                    mma_tf32(acc[mt][j], a0, a1, a2, a3, bfr[j][0], bfr[j][1]);
            }
        }
        __syncthreads();
    }

    // epilogue: relu + dot w2, reduce quad -> smem -> combine 2 n-warps
    float pr[2][2];
    pr[0][0] = pr[0][1] = pr[1][0] = pr[1][1] = 0.f;
    #pragma unroll
    for (int mt = 0; mt < 2; mt++) {
        #pragma unroll
        for (int j = 0; j < 8; j++) {
            int col = wn * 64 + j * 8 + 2 * c4;
            float w20 = sw2[col], w21 = sw2[col + 1];
            float b0 = sbe[col],  b1 = sbe[col + 1];
            pr[mt][0] += fmaxf(acc[mt][j][0] + b0, 0.f) * w20
                       + fmaxf(acc[mt][j][1] + b1, 0.f) * w21;
            pr[mt][1] += fmaxf(acc[mt][j][2] + b0, 0.f) * w20
                       + fmaxf(acc[mt][j][3] + b1, 0.f) * w21;
        }
    }
    #pragma unroll
    for (int off = 1; off < 4; off <<= 1) {
        pr[0][0] += __shfl_xor_sync(0xffffffffu, pr[0][0], off);
        pr[0][1] += __shfl_xor_sync(0xffffffffu, pr[0][1], off);
        pr[1][0] += __shfl_xor_sync(0xffffffffu, pr[1][0], off);
        pr[1][1] += __shfl_xor_sync(0xffffffffu, pr[1][1], off);
    }
    if (c4 == 0) {
        red[wm * 32 + r4][wn]       = pr[0][0];
        red[wm * 32 + 8 + r4][wn]   = pr[0][1];
        red[wm * 32 + 16 + r4][wn]  = pr[1][0];
        red[wm * 32 + 24 + r4][wn]  = pr[1][1];
    }
    __syncthreads();
    if (tid < 128) {
        int e = m0 + tid;
        if (e < E) {
            out[e] = red[tid][0] + red[tid][1]
                   + g_as[g_src[e]] + g_bs[g_dst[e]] + bout[0];
        }
    }
}

// ---------------- launch: kernel launches ONLY --------------------------------
extern "C" void kernel_launch(void* const* d_in, const int* in_sizes, int n_in,
                              void* d_out, int out_size) {
    const float* x    = (const float*)d_in[0];
    const int*   ei32 = (const int*)d_in[1];   // int32 OR int64 (detected on-device)
    const float* ea   = (const float*)d_in[2];
    const float* Wn   = (const float*)d_in[3];
    const float* bn   = (const float*)d_in[4];
    const float* We   = (const float*)d_in[5];
    const float* be   = (const float*)d_in[6];
    const float* Wzc  = (const float*)d_in[7];
    const float* bzc  = (const float*)d_in[8];
    const float* Wzl  = (const float*)d_in[9];
    const float* bzl  = (const float*)d_in[10];
    // d_in[11..14] = Wrc, brc, Wrl, brl  -- dead (H=0 makes R unused)
    const float* Whc  = (const float*)d_in[15];
    const float* bhc  = (const float*)d_in[16];
    const float* Whl  = (const float*)d_in[17];
    const float* bhl  = (const float*)d_in[18];
    const float* Wout = (const float*)d_in[19];
    const float* bout = (const float*)d_in[20];
    float* out = (float*)d_out;

    int nN = in_sizes[0] / S;      // 50000
    int nE = in_sizes[2] / 64;     // 800000
    int nScanBlocks = (nN + 255) / 256;   // 196

    // 0-2) dtype detect, zero histogram, decode (+in-degree count)
    ei_detect_k<<<1, 256>>>(ei32, nE);
    zero_cnt_k<<<(nN + 255) / 256, 256>>>(nN);
    ei_decode_k<<<(nE + 255) / 256, 256>>>(ei32, nE, nN);

    // 3) xe = relu(x@Wn+bn)   <-- launch index 3: ncu profile window
    xe_gemm_k<<<(nN + 127) / 128, 256>>>(x, Wn, bn, nN);

    // 4-6) CSR offsets: block scan, scan of block sums, combine (+dinv)
    scan1_k<<<nScanBlocks, 256>>>(nN);
    scan2_k<<<1, 256>>>(nScanBlocks);
    scan3_k<<<nScanBlocks, 256>>>(nN, nE);

    // 7-8) fold gate weights (independent, tiny)
    prep_w_k<<<128, 256>>>(Wzc, Wzl, Whc, Whl);
    prep_b_k<<<256, 128>>>(bzc, Wzl, bzl, bhc, Whl, bhl);

    // 9) group edges by destination (CSR fill)
    permute_k<<<(nE + 255) / 256, 256>>>(nE);

    // 10) gather: pxe = dinv^2*xe + sum cw*xe[src]   (no atomics)
    gather_k<<<(nN + 7) / 8, 256>>>(nN);

    // 11) fused: both gate GEMMs + GRU activation + w0/w1 dots -> g_as, g_bs
    zhab_gemm_k<<<(nN + 127) / 128, 256>>>(Wout, nN);

    // 12) fused edge GEMM (tf32 MMA) + reduction + gather
    edge_out_k<<<(nE + 127) / 128, 256>>>(ea, We, be, Wout, bout, out, nE);
}